// round 9
// baseline (speedup 1.0000x reference)
#include <cuda_runtime.h>
#include <math.h>

#define NN 100000
#define EE 1600000
#define HH 128
#define GG 64
#define SCAN_BLOCKS 391            // ceil(NN/256)

// ---------------- scratch (device globals; allocation-free) ----------------
__device__ float g_dinv[NN];
__device__ int   g_deg[NN];
__device__ int   g_csr_off[NN + 1];
__device__ int   g_csr_pos[NN];
__device__ int   g_csr_src[EE];
__device__ int   g_part[SCAN_BLOCKS];
__device__ float g_h[NN * HH];
__device__ float g_zs[NN * HH];
__device__ float g_agg[NN * HH];
__device__ float g_sum[HH];
__device__ float g_sumsq[HH];
__device__ float g_scale[HH];
__device__ float g_shift[HH];
__device__ float g_esc[NN];
__device__ float g_sumexp;
__device__ int   g_gstart[GG + 1];
__device__ float g_pooled[GG * HH];

// ---------------- f32x2 helpers (Blackwell packed FFMA2) ----------------
__device__ __forceinline__ unsigned long long dup2(float v) {
    unsigned long long r;
    unsigned int b = __float_as_uint(v);
    asm("mov.b64 %0, {%1, %1};" : "=l"(r) : "r"(b));
    return r;
}
__device__ __forceinline__ void fma2(unsigned long long& d, unsigned long long a,
                                     unsigned long long b) {
    asm("fma.rn.f32x2 %0, %1, %2, %3;" : "=l"(d) : "l"(a), "l"(b), "l"(d));
}
__device__ __forceinline__ float2 unpack2(unsigned long long v) {
    float2 r;
    asm("mov.b64 {%0, %1}, %2;" : "=f"(r.x), "=f"(r.y) : "l"(v));
    return r;
}

// ---------------- init / degree ----------------
__global__ void k_init() {
    int i = blockIdx.x * blockDim.x + threadIdx.x;
    if (i < NN) g_deg[i] = 0;
    if (i == 0) g_sumexp = 0.0f;
}

__global__ void k_count(const int* __restrict__ edst) {
    int e = blockIdx.x * blockDim.x + threadIdx.x;
    if (e < EE) atomicAdd(&g_deg[edst[e]], 1);
}

__global__ void k_rsqrt() {
    int i = blockIdx.x * blockDim.x + threadIdx.x;
    if (i < NN) g_dinv[i] = rsqrtf((float)g_deg[i] + 1.0f);   // +1 self loop
}

// ---------------- CSR build ----------------
__global__ __launch_bounds__(256) void k_scan1() {
    __shared__ int sh[256];
    int i = blockIdx.x * 256 + threadIdx.x;
    sh[threadIdx.x] = (i < NN) ? g_deg[i] : 0;
    __syncthreads();
    for (int s = 128; s > 0; s >>= 1) {
        if (threadIdx.x < s) sh[threadIdx.x] += sh[threadIdx.x + s];
        __syncthreads();
    }
    if (threadIdx.x == 0) g_part[blockIdx.x] = sh[0];
}

__global__ void k_scan2() {
    if (threadIdx.x == 0) {
        int run = 0;
        for (int b = 0; b < SCAN_BLOCKS; b++) {
            int v = g_part[b];
            g_part[b] = run;
            run += v;
        }
        g_csr_off[NN] = run;    // == EE
    }
}

__global__ __launch_bounds__(256) void k_scan3() {
    __shared__ int sh[256];
    int i = blockIdx.x * 256 + threadIdx.x;
    int v = (i < NN) ? g_deg[i] : 0;
    sh[threadIdx.x] = v;
    __syncthreads();
    for (int s = 1; s < 256; s <<= 1) {
        int t = (threadIdx.x >= s) ? sh[threadIdx.x - s] : 0;
        __syncthreads();
        sh[threadIdx.x] += t;
        __syncthreads();
    }
    if (i < NN) {
        int excl = sh[threadIdx.x] - v + g_part[blockIdx.x];
        g_csr_off[i] = excl;
        g_csr_pos[i] = excl;
    }
}

__global__ __launch_bounds__(256) void k_fill(const int* __restrict__ esrc,
                                              const int* __restrict__ edst) {
    int e = blockIdx.x * blockDim.x + threadIdx.x;
    if (e >= EE) return;
    int d = edst[e];
    int p = atomicAdd(&g_csr_pos[d], 1);
    g_csr_src[p] = esrc[e];
}

// ---------------- GEMM: z = A(N,128) @ W(128,128) --------------------------
// BM=256, 16x8 microtile, FFMA2, B-fragments register-held per k0 step.
// mode 0: g_zs = z*dinv[row];  g_agg = z*dinv^2 + bias[c]
// mode 1: fused attention score: g_esc[row] = exp(tanh(z+bias)·w2 + b2); sum->g_sumexp
#define BM 256
#define LDA 132
__global__ __launch_bounds__(256) void k_gemm(
    const float* __restrict__ Ain, const float* __restrict__ W,
    const float* __restrict__ bias,
    const float* __restrict__ w2, const float* __restrict__ b2,
    int mode)
{
    const float* A = (Ain == nullptr) ? g_h : Ain;
    extern __shared__ float sm[];
    float* sW = sm;                 // 128*128
    float* sA = sm + HH * HH;       // BM*LDA
    __shared__ float sh_e;
    int tid = threadIdx.x;
    int row0 = blockIdx.x * BM;
    if (tid == 0) sh_e = 0.0f;

    // load W (16384 floats = 4096 float4)
    {
        const float4* W4 = (const float4*)W;
        float4* sW4 = (float4*)sW;
#pragma unroll
        for (int t = 0; t < 16; t++) sW4[tid + t * 256] = W4[tid + t * 256];
    }
    // load A tile (256 rows x 128 = 8192 float4)
    {
#pragma unroll
        for (int t = 0; t < 32; t++) {
            int idx = tid + t * 256;          // 0..8191
            int r = idx >> 5, c4 = idx & 31;
            if (row0 + r < NN) {
                float4 v = *(const float4*)&A[(size_t)(row0 + r) * HH + c4 * 4];
                *(float4*)&sA[r * LDA + c4 * 4] = v;
            }
        }
    }
    __syncthreads();

    int tx = tid & 15, ty = tid >> 4;
    int cbase = tx * 8;
    unsigned long long acc[16][4];
#pragma unroll
    for (int i = 0; i < 16; i++)
#pragma unroll
        for (int j = 0; j < 4; j++) acc[i][j] = 0ull;

    for (int k0 = 0; k0 < HH; k0 += 4) {
        // hold all B fragments for this k0 step (4 kk x 4 ull = 32 regs)
        ulonglong2 b0[4], b1[4];
#pragma unroll
        for (int kk = 0; kk < 4; kk++) {
            b0[kk] = *(ulonglong2*)&sW[(k0 + kk) * HH + cbase];
            b1[kk] = *(ulonglong2*)&sW[(k0 + kk) * HH + cbase + 4];
        }
        // two row-groups of 8
#pragma unroll
        for (int g = 0; g < 2; g++) {
            float4 a[8];
#pragma unroll
            for (int i = 0; i < 8; i++)
                a[i] = *(float4*)&sA[(ty + (g * 8 + i) * 16) * LDA + k0];
#pragma unroll
            for (int kk = 0; kk < 4; kk++) {
#pragma unroll
                for (int i = 0; i < 8; i++) {
                    unsigned long long ad = dup2((&a[i].x)[kk]);
                    fma2(acc[g * 8 + i][0], ad, b0[kk].x);
                    fma2(acc[g * 8 + i][1], ad, b0[kk].y);
                    fma2(acc[g * 8 + i][2], ad, b1[kk].x);
                    fma2(acc[g * 8 + i][3], ad, b1[kk].y);
                }
            }
        }
    }

    float4 bv0 = ((const float4*)bias)[tx * 2];
    float4 bv1 = ((const float4*)bias)[tx * 2 + 1];
    float4 wv0, wv1;
    float b2v = 0.0f, esum = 0.0f;
    if (mode == 1) {
        wv0 = ((const float4*)w2)[tx * 2];
        wv1 = ((const float4*)w2)[tx * 2 + 1];
        b2v = b2[0];
    }

#pragma unroll
    for (int i = 0; i < 16; i++) {
        int row = row0 + ty + i * 16;
        float2 p0 = unpack2(acc[i][0]);
        float2 p1 = unpack2(acc[i][1]);
        float2 p2 = unpack2(acc[i][2]);
        float2 p3 = unpack2(acc[i][3]);
        float z[8] = {p0.x, p0.y, p1.x, p1.y, p2.x, p2.y, p3.x, p3.y};
        if (mode == 0) {
            if (row < NN) {
                size_t off = (size_t)row * HH + cbase;
                float di = g_dinv[row];
                float di2 = di * di;
                float4 z0 = make_float4(z[0] * di, z[1] * di, z[2] * di, z[3] * di);
                float4 z1 = make_float4(z[4] * di, z[5] * di, z[6] * di, z[7] * di);
                *(float4*)&g_zs[off]     = z0;
                *(float4*)&g_zs[off + 4] = z1;
                float4 q0 = make_float4(z[0] * di2 + bv0.x, z[1] * di2 + bv0.y,
                                        z[2] * di2 + bv0.z, z[3] * di2 + bv0.w);
                float4 q1 = make_float4(z[4] * di2 + bv1.x, z[5] * di2 + bv1.y,
                                        z[6] * di2 + bv1.z, z[7] * di2 + bv1.w);
                *(float4*)&g_agg[off]     = q0;
                *(float4*)&g_agg[off + 4] = q1;
            }
        } else {
            float t0 = tanhf(z[0] + bv0.x), t1 = tanhf(z[1] + bv0.y);
            float t2 = tanhf(z[2] + bv0.z), t3 = tanhf(z[3] + bv0.w);
            float t4 = tanhf(z[4] + bv1.x), t5 = tanhf(z[5] + bv1.y);
            float t6 = tanhf(z[6] + bv1.z), t7 = tanhf(z[7] + bv1.w);
            float part = t0 * wv0.x + t1 * wv0.y + t2 * wv0.z + t3 * wv0.w
                       + t4 * wv1.x + t5 * wv1.y + t6 * wv1.z + t7 * wv1.w;
#pragma unroll
            for (int off16 = 8; off16; off16 >>= 1)
                part += __shfl_xor_sync(0xffffffffu, part, off16);
            if ((tx == 0) && row < NN) {
                float e = expf(part + b2v);
                g_esc[row] = e;
                esum += e;
            }
        }
    }

    if (mode == 1) {
        if (tx == 0) atomicAdd(&sh_e, esum);
        __syncthreads();
        if (tid == 0) atomicAdd(&g_sumexp, sh_e);
    }
}

// ---------------- aggregate (CSR gather) + fused BN stats ----------------
// one warp per dst node (grid-stride) — R4-proven inner loop
#define AGG_BLOCKS 1184
__global__ __launch_bounds__(256) void k_aggregate() {
    int tid = threadIdx.x;
    int lane = tid & 31, warp = tid >> 5;
    int gw = blockIdx.x * 8 + warp;
    int nw = gridDim.x * 8;
    float4 s4 = make_float4(0, 0, 0, 0);
    float4 q4 = make_float4(0, 0, 0, 0);

    for (int node = gw; node < NN; node += nw) {
        int beg = g_csr_off[node], end = g_csr_off[node + 1];
        float4 acc = make_float4(0, 0, 0, 0);
        for (int base = beg; base < end; base += 32) {
            int idx = base + lane;
            int s = (idx < end) ? g_csr_src[idx] : 0;
            int cnt = min(32, end - base);
            for (int j = 0; j < cnt; j++) {
                int ss = __shfl_sync(0xffffffffu, s, j);
                float4 v = *(const float4*)&g_zs[(size_t)ss * HH + lane * 4];
                acc.x += v.x; acc.y += v.y; acc.z += v.z; acc.w += v.w;
            }
        }
        float di = g_dinv[node];
        float* rowp = &g_agg[(size_t)node * HH + lane * 4];
        float4 r = *(float4*)rowp;
        r.x += di * acc.x; r.y += di * acc.y; r.z += di * acc.z; r.w += di * acc.w;
        *(float4*)rowp = r;
        s4.x += r.x; s4.y += r.y; s4.z += r.z; s4.w += r.w;
        q4.x += r.x * r.x; q4.y += r.y * r.y; q4.z += r.z * r.z; q4.w += r.w * r.w;
    }

    __shared__ float sh[8][HH];
    ((float4*)sh[warp])[lane] = s4;
    __syncthreads();
    if (tid < HH) {
        float t = 0.0f;
#pragma unroll
        for (int w = 0; w < 8; w++) t += sh[w][tid];
        atomicAdd(&g_sum[tid], t);
    }
    __syncthreads();
    ((float4*)sh[warp])[lane] = q4;
    __syncthreads();
    if (tid < HH) {
        float t = 0.0f;
#pragma unroll
        for (int w = 0; w < 8; w++) t += sh[w][tid];
        atomicAdd(&g_sumsq[tid], t);
    }
}

// ---------------- batchnorm finalize / apply ----------------
__global__ void k_bnfin(const float* __restrict__ gamma, const float* __restrict__ beta) {
    int c = threadIdx.x;
    float mean = g_sum[c] / (float)NN;
    float var = g_sumsq[c] / (float)NN - mean * mean;
    float sc = rsqrtf(var + 1e-5f) * gamma[c];
    g_scale[c] = sc;
    g_shift[c] = beta[c] - mean * sc;
    g_sum[c] = 0.0f;
    g_sumsq[c] = 0.0f;
}

__global__ __launch_bounds__(256) void k_apply(int residual) {
    int i4 = blockIdx.x * blockDim.x + threadIdx.x;   // over NN*32 float4s
    if (i4 >= NN * 32) return;
    int c4 = i4 & 31;
    float4 v  = ((const float4*)g_agg)[i4];
    float4 sc = ((const float4*)g_scale)[c4];
    float4 sf = ((const float4*)g_shift)[c4];
    float4 r;
    r.x = fmaxf(v.x * sc.x + sf.x, 0.0f);
    r.y = fmaxf(v.y * sc.y + sf.y, 0.0f);
    r.z = fmaxf(v.z * sc.z + sf.z, 0.0f);
    r.w = fmaxf(v.w * sc.w + sf.w, 0.0f);
    if (residual) {
        float4 hv = ((const float4*)g_h)[i4];
        r.x += hv.x; r.y += hv.y; r.z += hv.z; r.w += hv.w;
    }
    ((float4*)g_h)[i4] = r;
}

// ---------------- graph offsets + zero pooled ----------------
__global__ void k_gstart(const int* __restrict__ batch) {
    int g = blockIdx.x, c = threadIdx.x;
    g_pooled[g * HH + c] = 0.0f;
    if (c == 0) {
        int lo = 0, hi = NN;
        while (lo < hi) {
            int m = (lo + hi) >> 1;
            if (batch[m] < g) lo = m + 1; else hi = m;
        }
        g_gstart[g] = lo;
        if (g == 0) g_gstart[GG] = NN;
    }
}

// ---------------- pooling (weighted sums) ----------------
__global__ void k_pool() {
    int g = blockIdx.x >> 3;
    int part = blockIdx.x & 7;
    int s = g_gstart[g], e = g_gstart[g + 1];
    int c = threadIdx.x;
    float acc = 0.0f;
    for (int r = s + part; r < e; r += 8)
        acc += g_h[(size_t)r * HH + c] * g_esc[r];
    atomicAdd(&g_pooled[g * HH + c], acc);
}

// ---------------- final MLP ----------------
__global__ void k_mlp(const float* __restrict__ W1, const float* __restrict__ b1,
                      const float* __restrict__ W2, const float* __restrict__ b2,
                      float* __restrict__ out)
{
    __shared__ float p[HH];
    __shared__ float t[HH];
    int g = blockIdx.x, c = threadIdx.x;
    int cnt = g_gstart[g + 1] - g_gstart[g];
    if (cnt < 1) cnt = 1;
    float inv = 1.0f / (g_sumexp * (float)cnt);
    p[c] = g_pooled[g * HH + c] * inv;
    __syncthreads();
    float acc = b1[c];
    for (int k = 0; k < HH; k++) acc += p[k] * W1[k * HH + c];
    t[c] = fmaxf(acc, 0.0f);
    __syncthreads();
    float acc2 = b2[c];
    for (int k = 0; k < HH; k++) acc2 += t[k] * W2[k * HH + c];
    out[g * HH + c] = acc2;
}

// ---------------- host ----------------
extern "C" void kernel_launch(void* const* d_in, const int* in_sizes, int n_in,
                              void* d_out, int out_size)
{
    const float* x      = (const float*)d_in[0];
    const int*   ei     = (const int*)d_in[1];   // [2, E] int32
    const int*   batch  = (const int*)d_in[2];
    const float* conv_w = (const float*)d_in[3];       // [3,128,128]
    const float* conv_b = (const float*)d_in[4];       // [3,128]
    const float* bn_g   = (const float*)d_in[5];
    const float* bn_b   = (const float*)d_in[6];
    const float* aw1    = (const float*)d_in[7];
    const float* ab1    = (const float*)d_in[8];
    const float* aw2    = (const float*)d_in[9];
    const float* ab2    = (const float*)d_in[10];
    const float* pw1    = (const float*)d_in[11];
    const float* pb1    = (const float*)d_in[12];
    const float* pw2    = (const float*)d_in[13];
    const float* pb2    = (const float*)d_in[14];
    float* out = (float*)d_out;

    const int smem = (HH * HH + BM * LDA) * sizeof(float);   // 200704 B
    cudaFuncSetAttribute(k_gemm, cudaFuncAttributeMaxDynamicSharedMemorySize, smem);

    const int gemm_grid = (NN + BM - 1) / BM;   // 391

    // degree / norm / CSR build
    k_init <<<(NN + 255) / 256, 256>>>();
    k_count<<<(EE + 255) / 256, 256>>>(ei + EE);
    k_rsqrt<<<(NN + 255) / 256, 256>>>();
    k_scan1<<<SCAN_BLOCKS, 256>>>();
    k_scan2<<<1, 32>>>();
    k_scan3<<<SCAN_BLOCKS, 256>>>();
    k_fill <<<(EE + 255) / 256, 256>>>(ei, ei + EE);

    // 3 GCN layers (separate apply — full-occupancy streaming)
    for (int i = 0; i < 3; i++) {
        const float* A = (i == 0) ? x : nullptr;   // nullptr -> g_h (device-side)
        k_gemm<<<gemm_grid, 256, smem>>>(A, conv_w + i * HH * HH, conv_b + i * HH,
                                         nullptr, nullptr, 0);
        k_aggregate<<<AGG_BLOCKS, 256>>>();
        k_bnfin<<<1, 128>>>(bn_g + i * HH, bn_b + i * HH);
        k_apply<<<(NN * 32 + 255) / 256, 256>>>(i > 0 ? 1 : 0);
    }

    // attention GEMM with fused score epilogue
    k_gemm<<<gemm_grid, 256, smem>>>(nullptr, aw1, ab1, aw2, ab2, 1);

    // pooling
    k_gstart<<<GG, 128>>>(batch);
    k_pool<<<GG * 8, 128>>>();

    // final MLP
    k_mlp<<<GG, 128>>>(pw1, pb1, pw2, pb2, out);
}

// round 10
// speedup vs baseline: 1.0227x; 1.0227x over previous
#include <cuda_runtime.h>
#include <math.h>

#define NN 100000
#define EE 1600000
#define HH 128
#define GG 64
#define SCAN_BLOCKS 391            // ceil(NN/256)

// ---------------- scratch (device globals; allocation-free) ----------------
__device__ float g_dinv[NN];
__device__ int   g_deg[NN];
__device__ int   g_csr_off[NN + 1];
__device__ int   g_csr_pos[NN];
__device__ int   g_csr_src[EE];
__device__ int   g_part[SCAN_BLOCKS];
__device__ float g_h[NN * HH];
__device__ float g_zs[NN * HH];
__device__ float g_agg[NN * HH];
__device__ float g_sum[HH];
__device__ float g_sumsq[HH];
__device__ float g_scale[HH];
__device__ float g_shift[HH];
__device__ float g_esc[NN];
__device__ float g_sumexp;
__device__ int   g_gstart[GG + 1];
__device__ float g_pooled[GG * HH];

// ---------------- f32x2 helpers (Blackwell packed FFMA2) ----------------
__device__ __forceinline__ unsigned long long dup2(float v) {
    unsigned long long r;
    unsigned int b = __float_as_uint(v);
    asm("mov.b64 %0, {%1, %1};" : "=l"(r) : "r"(b));
    return r;
}
__device__ __forceinline__ void fma2(unsigned long long& d, unsigned long long a,
                                     unsigned long long b) {
    asm("fma.rn.f32x2 %0, %1, %2, %3;" : "=l"(d) : "l"(a), "l"(b), "l"(d));
}
__device__ __forceinline__ float2 unpack2(unsigned long long v) {
    float2 r;
    asm("mov.b64 {%0, %1}, %2;" : "=f"(r.x), "=f"(r.y) : "l"(v));
    return r;
}

// ---------------- init / degree ----------------
__global__ void k_init() {
    int i = blockIdx.x * blockDim.x + threadIdx.x;
    if (i < NN) g_deg[i] = 0;
    if (i == 0) g_sumexp = 0.0f;
}

__global__ void k_count(const int* __restrict__ edst) {
    int e = blockIdx.x * blockDim.x + threadIdx.x;
    if (e < EE) atomicAdd(&g_deg[edst[e]], 1);
}

__global__ void k_rsqrt() {
    int i = blockIdx.x * blockDim.x + threadIdx.x;
    if (i < NN) g_dinv[i] = rsqrtf((float)g_deg[i] + 1.0f);   // +1 self loop
}

// ---------------- CSR build ----------------
__global__ __launch_bounds__(256) void k_scan1() {
    __shared__ int sh[256];
    int i = blockIdx.x * 256 + threadIdx.x;
    sh[threadIdx.x] = (i < NN) ? g_deg[i] : 0;
    __syncthreads();
    for (int s = 128; s > 0; s >>= 1) {
        if (threadIdx.x < s) sh[threadIdx.x] += sh[threadIdx.x + s];
        __syncthreads();
    }
    if (threadIdx.x == 0) g_part[blockIdx.x] = sh[0];
}

__global__ void k_scan2() {
    if (threadIdx.x == 0) {
        int run = 0;
        for (int b = 0; b < SCAN_BLOCKS; b++) {
            int v = g_part[b];
            g_part[b] = run;
            run += v;
        }
        g_csr_off[NN] = run;    // == EE
    }
}

__global__ __launch_bounds__(256) void k_scan3() {
    __shared__ int sh[256];
    int i = blockIdx.x * 256 + threadIdx.x;
    int v = (i < NN) ? g_deg[i] : 0;
    sh[threadIdx.x] = v;
    __syncthreads();
    for (int s = 1; s < 256; s <<= 1) {
        int t = (threadIdx.x >= s) ? sh[threadIdx.x - s] : 0;
        __syncthreads();
        sh[threadIdx.x] += t;
        __syncthreads();
    }
    if (i < NN) {
        int excl = sh[threadIdx.x] - v + g_part[blockIdx.x];
        g_csr_off[i] = excl;
        g_csr_pos[i] = excl;
    }
}

__global__ __launch_bounds__(256) void k_fill(const int* __restrict__ esrc,
                                              const int* __restrict__ edst) {
    int e = blockIdx.x * blockDim.x + threadIdx.x;
    if (e >= EE) return;
    int d = edst[e];
    int p = atomicAdd(&g_csr_pos[d], 1);
    g_csr_src[p] = esrc[e];
}

// ---------------- GEMM: z = A(N,128) @ W(128,128) --------------------------
// BM=128, 8x8 microtile, FFMA2 (R4/R8-proven shape — FROZEN).
// mode 0: g_zs = z*dinv[row];  g_agg = z*dinv^2 + bias[c]
// mode 1: fused attention score: g_esc[row] = exp(tanh(z+bias)·w2 + b2); sum->g_sumexp
#define BM 128
#define LDA 132
__global__ __launch_bounds__(256) void k_gemm(
    const float* __restrict__ Ain, const float* __restrict__ W,
    const float* __restrict__ bias,
    const float* __restrict__ w2, const float* __restrict__ b2,
    int mode)
{
    const float* A = (Ain == nullptr) ? g_h : Ain;
    extern __shared__ float sm[];
    float* sW = sm;                 // 128*128
    float* sA = sm + HH * HH;       // BM*LDA
    __shared__ float sh_e;
    int tid = threadIdx.x;
    int row0 = blockIdx.x * BM;
    if (tid == 0) sh_e = 0.0f;

    // load W (16384 floats = 4096 float4)
    {
        const float4* W4 = (const float4*)W;
        float4* sW4 = (float4*)sW;
#pragma unroll
        for (int t = 0; t < 16; t++) sW4[tid + t * 256] = W4[tid + t * 256];
    }
    // load A tile (128 rows x 128)
    {
#pragma unroll
        for (int t = 0; t < 16; t++) {
            int idx = tid + t * 256;          // 0..4095
            int r = idx >> 5, c4 = idx & 31;
            if (row0 + r < NN) {
                float4 v = *(const float4*)&A[(size_t)(row0 + r) * HH + c4 * 4];
                *(float4*)&sA[r * LDA + c4 * 4] = v;
            }
        }
    }
    __syncthreads();

    int tx = tid & 15, ty = tid >> 4;
    int cbase = tx * 8;
    unsigned long long acc[8][4];
#pragma unroll
    for (int i = 0; i < 8; i++)
#pragma unroll
        for (int j = 0; j < 4; j++) acc[i][j] = 0ull;

#pragma unroll 4
    for (int k0 = 0; k0 < HH; k0 += 4) {
        float4 a[8];
#pragma unroll
        for (int i = 0; i < 8; i++)
            a[i] = *(float4*)&sA[(ty + i * 16) * LDA + k0];
#pragma unroll
        for (int kk = 0; kk < 4; kk++) {
            ulonglong2 b0 = *(ulonglong2*)&sW[(k0 + kk) * HH + cbase];
            ulonglong2 b1 = *(ulonglong2*)&sW[(k0 + kk) * HH + cbase + 4];
#pragma unroll
            for (int i = 0; i < 8; i++) {
                unsigned long long ad = dup2((&a[i].x)[kk]);
                fma2(acc[i][0], ad, b0.x);
                fma2(acc[i][1], ad, b0.y);
                fma2(acc[i][2], ad, b1.x);
                fma2(acc[i][3], ad, b1.y);
            }
        }
    }

    float4 bv0 = ((const float4*)bias)[tx * 2];
    float4 bv1 = ((const float4*)bias)[tx * 2 + 1];
    float4 wv0, wv1;
    float b2v = 0.0f, esum = 0.0f;
    if (mode == 1) {
        wv0 = ((const float4*)w2)[tx * 2];
        wv1 = ((const float4*)w2)[tx * 2 + 1];
        b2v = b2[0];
    }

#pragma unroll
    for (int i = 0; i < 8; i++) {
        int row = row0 + ty + i * 16;
        float2 p0 = unpack2(acc[i][0]);
        float2 p1 = unpack2(acc[i][1]);
        float2 p2 = unpack2(acc[i][2]);
        float2 p3 = unpack2(acc[i][3]);
        float z[8] = {p0.x, p0.y, p1.x, p1.y, p2.x, p2.y, p3.x, p3.y};
        if (mode == 0) {
            if (row < NN) {
                size_t off = (size_t)row * HH + cbase;
                float di = g_dinv[row];
                float di2 = di * di;
                float4 z0 = make_float4(z[0] * di, z[1] * di, z[2] * di, z[3] * di);
                float4 z1 = make_float4(z[4] * di, z[5] * di, z[6] * di, z[7] * di);
                *(float4*)&g_zs[off]     = z0;
                *(float4*)&g_zs[off + 4] = z1;
                float4 q0 = make_float4(z[0] * di2 + bv0.x, z[1] * di2 + bv0.y,
                                        z[2] * di2 + bv0.z, z[3] * di2 + bv0.w);
                float4 q1 = make_float4(z[4] * di2 + bv1.x, z[5] * di2 + bv1.y,
                                        z[6] * di2 + bv1.z, z[7] * di2 + bv1.w);
                *(float4*)&g_agg[off]     = q0;
                *(float4*)&g_agg[off + 4] = q1;
            }
        } else {
            float t0 = tanhf(z[0] + bv0.x), t1 = tanhf(z[1] + bv0.y);
            float t2 = tanhf(z[2] + bv0.z), t3 = tanhf(z[3] + bv0.w);
            float t4 = tanhf(z[4] + bv1.x), t5 = tanhf(z[5] + bv1.y);
            float t6 = tanhf(z[6] + bv1.z), t7 = tanhf(z[7] + bv1.w);
            float part = t0 * wv0.x + t1 * wv0.y + t2 * wv0.z + t3 * wv0.w
                       + t4 * wv1.x + t5 * wv1.y + t6 * wv1.z + t7 * wv1.w;
#pragma unroll
            for (int off16 = 8; off16; off16 >>= 1)
                part += __shfl_xor_sync(0xffffffffu, part, off16);
            if ((tx == 0) && row < NN) {
                float e = expf(part + b2v);
                g_esc[row] = e;
                esum += e;
            }
        }
    }

    if (mode == 1) {
        if (tx == 0) atomicAdd(&sh_e, esum);
        __syncthreads();
        if (tid == 0) atomicAdd(&g_sumexp, sh_e);
    }
}

// ---------------- aggregate (CSR gather) + fused BN stats ----------------
// one warp per dst node; dual accumulator chains + 2-edge unroll (this
// round's single change): two independent LDG.128s in flight and two
// independent FADD chains per lane.
#define AGG_BLOCKS 1184
__global__ __launch_bounds__(256) void k_aggregate() {
    int tid = threadIdx.x;
    int lane = tid & 31, warp = tid >> 5;
    int gw = blockIdx.x * 8 + warp;
    int nw = gridDim.x * 8;
    float4 s4 = make_float4(0, 0, 0, 0);
    float4 q4 = make_float4(0, 0, 0, 0);

    for (int node = gw; node < NN; node += nw) {
        int beg = g_csr_off[node], end = g_csr_off[node + 1];
        float4 a0 = make_float4(0, 0, 0, 0);
        float4 a1 = make_float4(0, 0, 0, 0);
        for (int base = beg; base < end; base += 32) {
            int idx = base + lane;
            int s = (idx < end) ? g_csr_src[idx] : 0;
            int cnt = min(32, end - base);
            int j = 0;
            for (; j + 2 <= cnt; j += 2) {
                int s0 = __shfl_sync(0xffffffffu, s, j);
                int s1 = __shfl_sync(0xffffffffu, s, j + 1);
                float4 v0 = *(const float4*)&g_zs[(size_t)s0 * HH + lane * 4];
                float4 v1 = *(const float4*)&g_zs[(size_t)s1 * HH + lane * 4];
                a0.x += v0.x; a0.y += v0.y; a0.z += v0.z; a0.w += v0.w;
                a1.x += v1.x; a1.y += v1.y; a1.z += v1.z; a1.w += v1.w;
            }
            if (j < cnt) {
                int ss = __shfl_sync(0xffffffffu, s, j);
                float4 v = *(const float4*)&g_zs[(size_t)ss * HH + lane * 4];
                a0.x += v.x; a0.y += v.y; a0.z += v.z; a0.w += v.w;
            }
        }
        float4 acc = make_float4(a0.x + a1.x, a0.y + a1.y,
                                 a0.z + a1.z, a0.w + a1.w);
        float di = g_dinv[node];
        float* rowp = &g_agg[(size_t)node * HH + lane * 4];
        float4 r = *(float4*)rowp;
        r.x += di * acc.x; r.y += di * acc.y; r.z += di * acc.z; r.w += di * acc.w;
        *(float4*)rowp = r;
        s4.x += r.x; s4.y += r.y; s4.z += r.z; s4.w += r.w;
        q4.x += r.x * r.x; q4.y += r.y * r.y; q4.z += r.z * r.z; q4.w += r.w * r.w;
    }

    __shared__ float sh[8][HH];
    ((float4*)sh[warp])[lane] = s4;
    __syncthreads();
    if (tid < HH) {
        float t = 0.0f;
#pragma unroll
        for (int w = 0; w < 8; w++) t += sh[w][tid];
        atomicAdd(&g_sum[tid], t);
    }
    __syncthreads();
    ((float4*)sh[warp])[lane] = q4;
    __syncthreads();
    if (tid < HH) {
        float t = 0.0f;
#pragma unroll
        for (int w = 0; w < 8; w++) t += sh[w][tid];
        atomicAdd(&g_sumsq[tid], t);
    }
}

// ---------------- batchnorm finalize / apply ----------------
__global__ void k_bnfin(const float* __restrict__ gamma, const float* __restrict__ beta) {
    int c = threadIdx.x;
    float mean = g_sum[c] / (float)NN;
    float var = g_sumsq[c] / (float)NN - mean * mean;
    float sc = rsqrtf(var + 1e-5f) * gamma[c];
    g_scale[c] = sc;
    g_shift[c] = beta[c] - mean * sc;
    g_sum[c] = 0.0f;
    g_sumsq[c] = 0.0f;
}

__global__ __launch_bounds__(256) void k_apply(int residual) {
    int i4 = blockIdx.x * blockDim.x + threadIdx.x;   // over NN*32 float4s
    if (i4 >= NN * 32) return;
    int c4 = i4 & 31;
    float4 v  = ((const float4*)g_agg)[i4];
    float4 sc = ((const float4*)g_scale)[c4];
    float4 sf = ((const float4*)g_shift)[c4];
    float4 r;
    r.x = fmaxf(v.x * sc.x + sf.x, 0.0f);
    r.y = fmaxf(v.y * sc.y + sf.y, 0.0f);
    r.z = fmaxf(v.z * sc.z + sf.z, 0.0f);
    r.w = fmaxf(v.w * sc.w + sf.w, 0.0f);
    if (residual) {
        float4 hv = ((const float4*)g_h)[i4];
        r.x += hv.x; r.y += hv.y; r.z += hv.z; r.w += hv.w;
    }
    ((float4*)g_h)[i4] = r;
}

// ---------------- graph offsets + zero pooled ----------------
__global__ void k_gstart(const int* __restrict__ batch) {
    int g = blockIdx.x, c = threadIdx.x;
    g_pooled[g * HH + c] = 0.0f;
    if (c == 0) {
        int lo = 0, hi = NN;
        while (lo < hi) {
            int m = (lo + hi) >> 1;
            if (batch[m] < g) lo = m + 1; else hi = m;
        }
        g_gstart[g] = lo;
        if (g == 0) g_gstart[GG] = NN;
    }
}

// ---------------- pooling (weighted sums) ----------------
__global__ void k_pool() {
    int g = blockIdx.x >> 3;
    int part = blockIdx.x & 7;
    int s = g_gstart[g], e = g_gstart[g + 1];
    int c = threadIdx.x;
    float acc = 0.0f;
    for (int r = s + part; r < e; r += 8)
        acc += g_h[(size_t)r * HH + c] * g_esc[r];
    atomicAdd(&g_pooled[g * HH + c], acc);
}

// ---------------- final MLP ----------------
__global__ void k_mlp(const float* __restrict__ W1, const float* __restrict__ b1,
                      const float* __restrict__ W2, const float* __restrict__ b2,
                      float* __restrict__ out)
{
    __shared__ float p[HH];
    __shared__ float t[HH];
    int g = blockIdx.x, c = threadIdx.x;
    int cnt = g_gstart[g + 1] - g_gstart[g];
    if (cnt < 1) cnt = 1;
    float inv = 1.0f / (g_sumexp * (float)cnt);
    p[c] = g_pooled[g * HH + c] * inv;
    __syncthreads();
    float acc = b1[c];
    for (int k = 0; k < HH; k++) acc += p[k] * W1[k * HH + c];
    t[c] = fmaxf(acc, 0.0f);
    __syncthreads();
    float acc2 = b2[c];
    for (int k = 0; k < HH; k++) acc2 += t[k] * W2[k * HH + c];
    out[g * HH + c] = acc2;
}

// ---------------- host ----------------
extern "C" void kernel_launch(void* const* d_in, const int* in_sizes, int n_in,
                              void* d_out, int out_size)
{
    const float* x      = (const float*)d_in[0];
    const int*   ei     = (const int*)d_in[1];   // [2, E] int32
    const int*   batch  = (const int*)d_in[2];
    const float* conv_w = (const float*)d_in[3];       // [3,128,128]
    const float* conv_b = (const float*)d_in[4];       // [3,128]
    const float* bn_g   = (const float*)d_in[5];
    const float* bn_b   = (const float*)d_in[6];
    const float* aw1    = (const float*)d_in[7];
    const float* ab1    = (const float*)d_in[8];
    const float* aw2    = (const float*)d_in[9];
    const float* ab2    = (const float*)d_in[10];
    const float* pw1    = (const float*)d_in[11];
    const float* pb1    = (const float*)d_in[12];
    const float* pw2    = (const float*)d_in[13];
    const float* pb2    = (const float*)d_in[14];
    float* out = (float*)d_out;

    const int smem = (HH * HH + BM * LDA) * sizeof(float);   // 133120 B
    cudaFuncSetAttribute(k_gemm, cudaFuncAttributeMaxDynamicSharedMemorySize, smem);

    const int gemm_grid = (NN + BM - 1) / BM;   // 782

    // degree / norm / CSR build
    k_init <<<(NN + 255) / 256, 256>>>();
    k_count<<<(EE + 255) / 256, 256>>>(ei + EE);
    k_rsqrt<<<(NN + 255) / 256, 256>>>();
    k_scan1<<<SCAN_BLOCKS, 256>>>();
    k_scan2<<<1, 32>>>();
    k_scan3<<<SCAN_BLOCKS, 256>>>();
    k_fill <<<(EE + 255) / 256, 256>>>(ei, ei + EE);

    // 3 GCN layers (separate apply — full-occupancy streaming)
    for (int i = 0; i < 3; i++) {
        const float* A = (i == 0) ? x : nullptr;   // nullptr -> g_h (device-side)
        k_gemm<<<gemm_grid, 256, smem>>>(A, conv_w + i * HH * HH, conv_b + i * HH,
                                         nullptr, nullptr, 0);
        k_aggregate<<<AGG_BLOCKS, 256>>>();
        k_bnfin<<<1, 128>>>(bn_g + i * HH, bn_b + i * HH);
        k_apply<<<(NN * 32 + 255) / 256, 256>>>(i > 0 ? 1 : 0);
    }

    // attention GEMM with fused score epilogue
    k_gemm<<<gemm_grid, 256, smem>>>(nullptr, aw1, ab1, aw2, ab2, 1);

    // pooling
    k_gstart<<<GG, 128>>>(batch);
    k_pool<<<GG * 8, 128>>>();

    // final MLP
    k_mlp<<<GG, 128>>>(pw1, pb1, pw2, pb2, out);
}

// round 11
// speedup vs baseline: 1.0637x; 1.0402x over previous
#include <cuda_runtime.h>
#include <math.h>

#define NN 100000
#define EE 1600000
#define HH 128
#define GG 64
#define SCAN_BLOCKS 391            // ceil(NN/256)

// ---------------- scratch (device globals; allocation-free) ----------------
__device__ float g_dinv[NN];
__device__ int   g_deg[NN];
__device__ int   g_csr_off[NN + 1];
__device__ int   g_csr_pos[NN];
__device__ int   g_csr_src[EE];
__device__ int   g_part[SCAN_BLOCKS];
__device__ float g_h[NN * HH];
__device__ float g_zs[NN * HH];
__device__ float g_agg[NN * HH];
__device__ float g_sum[HH];
__device__ float g_sumsq[HH];
__device__ float g_scale[HH];
__device__ float g_shift[HH];
__device__ float g_esc[NN];
__device__ float g_sumexp;
__device__ int   g_gstart[GG + 1];
__device__ float g_pooled[GG * HH];

// ---------------- f32x2 helpers (Blackwell packed FFMA2) ----------------
__device__ __forceinline__ unsigned long long dup2(float v) {
    unsigned long long r;
    unsigned int b = __float_as_uint(v);
    asm("mov.b64 %0, {%1, %1};" : "=l"(r) : "r"(b));
    return r;
}
__device__ __forceinline__ void fma2(unsigned long long& d, unsigned long long a,
                                     unsigned long long b) {
    asm("fma.rn.f32x2 %0, %1, %2, %3;" : "=l"(d) : "l"(a), "l"(b), "l"(d));
}
__device__ __forceinline__ float2 unpack2(unsigned long long v) {
    float2 r;
    asm("mov.b64 {%0, %1}, %2;" : "=f"(r.x), "=f"(r.y) : "l"(v));
    return r;
}
__device__ __forceinline__ void cp_async16(float* smem_dst, const float* gsrc) {
    unsigned int s = (unsigned int)__cvta_generic_to_shared(smem_dst);
    asm volatile("cp.async.cg.shared.global [%0], [%1], 16;" :: "r"(s), "l"(gsrc));
}

// ---------------- init / degree ----------------
__global__ void k_init() {
    int i = blockIdx.x * blockDim.x + threadIdx.x;
    if (i < NN) g_deg[i] = 0;
    if (i == 0) g_sumexp = 0.0f;
}

__global__ void k_count(const int* __restrict__ edst) {
    int e = blockIdx.x * blockDim.x + threadIdx.x;
    if (e < EE) atomicAdd(&g_deg[edst[e]], 1);
}

__global__ void k_rsqrt() {
    int i = blockIdx.x * blockDim.x + threadIdx.x;
    if (i < NN) g_dinv[i] = rsqrtf((float)g_deg[i] + 1.0f);   // +1 self loop
}

// ---------------- CSR build ----------------
__global__ __launch_bounds__(256) void k_scan1() {
    __shared__ int sh[256];
    int i = blockIdx.x * 256 + threadIdx.x;
    sh[threadIdx.x] = (i < NN) ? g_deg[i] : 0;
    __syncthreads();
    for (int s = 128; s > 0; s >>= 1) {
        if (threadIdx.x < s) sh[threadIdx.x] += sh[threadIdx.x + s];
        __syncthreads();
    }
    if (threadIdx.x == 0) g_part[blockIdx.x] = sh[0];
}

__global__ void k_scan2() {
    if (threadIdx.x == 0) {
        int run = 0;
        for (int b = 0; b < SCAN_BLOCKS; b++) {
            int v = g_part[b];
            g_part[b] = run;
            run += v;
        }
        g_csr_off[NN] = run;    // == EE
    }
}

__global__ __launch_bounds__(256) void k_scan3() {
    __shared__ int sh[256];
    int i = blockIdx.x * 256 + threadIdx.x;
    int v = (i < NN) ? g_deg[i] : 0;
    sh[threadIdx.x] = v;
    __syncthreads();
    for (int s = 1; s < 256; s <<= 1) {
        int t = (threadIdx.x >= s) ? sh[threadIdx.x - s] : 0;
        __syncthreads();
        sh[threadIdx.x] += t;
        __syncthreads();
    }
    if (i < NN) {
        int excl = sh[threadIdx.x] - v + g_part[blockIdx.x];
        g_csr_off[i] = excl;
        g_csr_pos[i] = excl;
    }
}

__global__ __launch_bounds__(256) void k_fill(const int* __restrict__ esrc,
                                              const int* __restrict__ edst) {
    int e = blockIdx.x * blockDim.x + threadIdx.x;
    if (e >= EE) return;
    int d = edst[e];
    int p = atomicAdd(&g_csr_pos[d], 1);
    g_csr_src[p] = esrc[e];
}

// ---------------- GEMM: z = A(N,128) @ W(128,128) --------------------------
// PERSISTENT (grid=148) + cp.async double-buffered A tiles.
// Inner compute: BM=128 tile, 8x8 microtile, FFMA2 (R4/R8-proven — unchanged).
// mode 0: g_zs = z*dinv[row];  g_agg = z*dinv^2 + bias[c]
// mode 1: fused attention score: g_esc[row] = exp(tanh(z+bias)·w2 + b2); sum->g_sumexp
#define BM 128
#define LDA 132
#define GEMM_GRID 148

__device__ __forceinline__ void load_tile_async(float* sA, const float* A, int row0) {
#pragma unroll
    for (int t = 0; t < 16; t++) {
        int idx = threadIdx.x + t * 256;       // 0..4095
        int r = idx >> 5, c4 = idx & 31;
        if (row0 + r < NN)
            cp_async16(&sA[r * LDA + c4 * 4], &A[(size_t)(row0 + r) * HH + c4 * 4]);
    }
}

__global__ __launch_bounds__(256) void k_gemm(
    const float* __restrict__ Ain, const float* __restrict__ W,
    const float* __restrict__ bias,
    const float* __restrict__ w2, const float* __restrict__ b2,
    int mode)
{
    const float* A = (Ain == nullptr) ? g_h : Ain;
    extern __shared__ float sm[];
    float* sW  = sm;                       // 128*128
    float* sA0 = sm + HH * HH;             // BM*LDA
    float* sA1 = sA0 + BM * LDA;           // BM*LDA
    __shared__ float sh_e;
    int tid = threadIdx.x;
    if (tid == 0) sh_e = 0.0f;

    // load W once (16384 floats = 4096 float4)
    {
        const float4* W4 = (const float4*)W;
        float4* sW4 = (float4*)sW;
#pragma unroll
        for (int t = 0; t < 16; t++) sW4[tid + t * 256] = W4[tid + t * 256];
    }

    const int NT = (NN + BM - 1) / BM;     // 782
    int tx = tid & 15, ty = tid >> 4;
    int cbase = tx * 8;

    float4 bv0 = ((const float4*)bias)[tx * 2];
    float4 bv1 = ((const float4*)bias)[tx * 2 + 1];
    float4 wv0 = make_float4(0, 0, 0, 0), wv1 = make_float4(0, 0, 0, 0);
    float b2v = 0.0f, esum = 0.0f;
    if (mode == 1) {
        wv0 = ((const float4*)w2)[tx * 2];
        wv1 = ((const float4*)w2)[tx * 2 + 1];
        b2v = b2[0];
    }

    // prefetch first tile
    load_tile_async(sA0, A, blockIdx.x * BM);
    asm volatile("cp.async.commit_group;");

    int cur = 0;
    for (int tile = blockIdx.x; tile < NT; tile += GEMM_GRID) {
        float* sA = cur ? sA1 : sA0;
        float* sAn = cur ? sA0 : sA1;
        int next = tile + GEMM_GRID;
        if (next < NT) {
            load_tile_async(sAn, A, next * BM);
            asm volatile("cp.async.commit_group;");
            asm volatile("cp.async.wait_group 1;");
        } else {
            asm volatile("cp.async.wait_group 0;");
        }
        __syncthreads();   // current tile (and W on first iter) visible to all

        int row0 = tile * BM;
        unsigned long long acc[8][4];
#pragma unroll
        for (int i = 0; i < 8; i++)
#pragma unroll
            for (int j = 0; j < 4; j++) acc[i][j] = 0ull;

#pragma unroll 4
        for (int k0 = 0; k0 < HH; k0 += 4) {
            float4 a[8];
#pragma unroll
            for (int i = 0; i < 8; i++)
                a[i] = *(float4*)&sA[(ty + i * 16) * LDA + k0];
#pragma unroll
            for (int kk = 0; kk < 4; kk++) {
                ulonglong2 b0 = *(ulonglong2*)&sW[(k0 + kk) * HH + cbase];
                ulonglong2 b1 = *(ulonglong2*)&sW[(k0 + kk) * HH + cbase + 4];
#pragma unroll
                for (int i = 0; i < 8; i++) {
                    unsigned long long ad = dup2((&a[i].x)[kk]);
                    fma2(acc[i][0], ad, b0.x);
                    fma2(acc[i][1], ad, b0.y);
                    fma2(acc[i][2], ad, b1.x);
                    fma2(acc[i][3], ad, b1.y);
                }
            }
        }

#pragma unroll
        for (int i = 0; i < 8; i++) {
            int row = row0 + ty + i * 16;
            float2 p0 = unpack2(acc[i][0]);
            float2 p1 = unpack2(acc[i][1]);
            float2 p2 = unpack2(acc[i][2]);
            float2 p3 = unpack2(acc[i][3]);
            float z[8] = {p0.x, p0.y, p1.x, p1.y, p2.x, p2.y, p3.x, p3.y};
            if (mode == 0) {
                if (row < NN) {
                    size_t off = (size_t)row * HH + cbase;
                    float di = g_dinv[row];
                    float di2 = di * di;
                    float4 z0 = make_float4(z[0] * di, z[1] * di, z[2] * di, z[3] * di);
                    float4 z1 = make_float4(z[4] * di, z[5] * di, z[6] * di, z[7] * di);
                    *(float4*)&g_zs[off]     = z0;
                    *(float4*)&g_zs[off + 4] = z1;
                    float4 q0 = make_float4(z[0] * di2 + bv0.x, z[1] * di2 + bv0.y,
                                            z[2] * di2 + bv0.z, z[3] * di2 + bv0.w);
                    float4 q1 = make_float4(z[4] * di2 + bv1.x, z[5] * di2 + bv1.y,
                                            z[6] * di2 + bv1.z, z[7] * di2 + bv1.w);
                    *(float4*)&g_agg[off]     = q0;
                    *(float4*)&g_agg[off + 4] = q1;
                }
            } else {
                float t0 = tanhf(z[0] + bv0.x), t1 = tanhf(z[1] + bv0.y);
                float t2 = tanhf(z[2] + bv0.z), t3 = tanhf(z[3] + bv0.w);
                float t4 = tanhf(z[4] + bv1.x), t5 = tanhf(z[5] + bv1.y);
                float t6 = tanhf(z[6] + bv1.z), t7 = tanhf(z[7] + bv1.w);
                float part = t0 * wv0.x + t1 * wv0.y + t2 * wv0.z + t3 * wv0.w
                           + t4 * wv1.x + t5 * wv1.y + t6 * wv1.z + t7 * wv1.w;
#pragma unroll
                for (int off16 = 8; off16; off16 >>= 1)
                    part += __shfl_xor_sync(0xffffffffu, part, off16);
                if ((tx == 0) && row < NN) {
                    float e = expf(part + b2v);
                    g_esc[row] = e;
                    esum += e;
                }
            }
        }

        __syncthreads();   // all warps done reading sA before it is refilled
        cur ^= 1;
    }

    if (mode == 1) {
        if (tx == 0) atomicAdd(&sh_e, esum);
        __syncthreads();
        if (tid == 0) atomicAdd(&g_sumexp, sh_e);
    }
}

// ---------------- aggregate (CSR gather) + fused BN stats ----------------
// one warp per dst node (grid-stride) — R4/R8-proven inner loop (FROZEN)
#define AGG_BLOCKS 1184
__global__ __launch_bounds__(256) void k_aggregate() {
    int tid = threadIdx.x;
    int lane = tid & 31, warp = tid >> 5;
    int gw = blockIdx.x * 8 + warp;
    int nw = gridDim.x * 8;
    float4 s4 = make_float4(0, 0, 0, 0);
    float4 q4 = make_float4(0, 0, 0, 0);

    for (int node = gw; node < NN; node += nw) {
        int beg = g_csr_off[node], end = g_csr_off[node + 1];
        float4 acc = make_float4(0, 0, 0, 0);
        for (int base = beg; base < end; base += 32) {
            int idx = base + lane;
            int s = (idx < end) ? g_csr_src[idx] : 0;
            int cnt = min(32, end - base);
            for (int j = 0; j < cnt; j++) {
                int ss = __shfl_sync(0xffffffffu, s, j);
                float4 v = *(const float4*)&g_zs[(size_t)ss * HH + lane * 4];
                acc.x += v.x; acc.y += v.y; acc.z += v.z; acc.w += v.w;
            }
        }
        float di = g_dinv[node];
        float* rowp = &g_agg[(size_t)node * HH + lane * 4];
        float4 r = *(float4*)rowp;
        r.x += di * acc.x; r.y += di * acc.y; r.z += di * acc.z; r.w += di * acc.w;
        *(float4*)rowp = r;
        s4.x += r.x; s4.y += r.y; s4.z += r.z; s4.w += r.w;
        q4.x += r.x * r.x; q4.y += r.y * r.y; q4.z += r.z * r.z; q4.w += r.w * r.w;
    }

    __shared__ float sh[8][HH];
    ((float4*)sh[warp])[lane] = s4;
    __syncthreads();
    if (tid < HH) {
        float t = 0.0f;
#pragma unroll
        for (int w = 0; w < 8; w++) t += sh[w][tid];
        atomicAdd(&g_sum[tid], t);
    }
    __syncthreads();
    ((float4*)sh[warp])[lane] = q4;
    __syncthreads();
    if (tid < HH) {
        float t = 0.0f;
#pragma unroll
        for (int w = 0; w < 8; w++) t += sh[w][tid];
        atomicAdd(&g_sumsq[tid], t);
    }
}

// ---------------- batchnorm finalize / apply ----------------
__global__ void k_bnfin(const float* __restrict__ gamma, const float* __restrict__ beta) {
    int c = threadIdx.x;
    float mean = g_sum[c] / (float)NN;
    float var = g_sumsq[c] / (float)NN - mean * mean;
    float sc = rsqrtf(var + 1e-5f) * gamma[c];
    g_scale[c] = sc;
    g_shift[c] = beta[c] - mean * sc;
    g_sum[c] = 0.0f;
    g_sumsq[c] = 0.0f;
}

__global__ __launch_bounds__(256) void k_apply(int residual) {
    int i4 = blockIdx.x * blockDim.x + threadIdx.x;   // over NN*32 float4s
    if (i4 >= NN * 32) return;
    int c4 = i4 & 31;
    float4 v  = ((const float4*)g_agg)[i4];
    float4 sc = ((const float4*)g_scale)[c4];
    float4 sf = ((const float4*)g_shift)[c4];
    float4 r;
    r.x = fmaxf(v.x * sc.x + sf.x, 0.0f);
    r.y = fmaxf(v.y * sc.y + sf.y, 0.0f);
    r.z = fmaxf(v.z * sc.z + sf.z, 0.0f);
    r.w = fmaxf(v.w * sc.w + sf.w, 0.0f);
    if (residual) {
        float4 hv = ((const float4*)g_h)[i4];
        r.x += hv.x; r.y += hv.y; r.z += hv.z; r.w += hv.w;
    }
    ((float4*)g_h)[i4] = r;
}

// ---------------- graph offsets + zero pooled ----------------
__global__ void k_gstart(const int* __restrict__ batch) {
    int g = blockIdx.x, c = threadIdx.x;
    g_pooled[g * HH + c] = 0.0f;
    if (c == 0) {
        int lo = 0, hi = NN;
        while (lo < hi) {
            int m = (lo + hi) >> 1;
            if (batch[m] < g) lo = m + 1; else hi = m;
        }
        g_gstart[g] = lo;
        if (g == 0) g_gstart[GG] = NN;
    }
}

// ---------------- pooling (weighted sums) ----------------
__global__ void k_pool() {
    int g = blockIdx.x >> 3;
    int part = blockIdx.x & 7;
    int s = g_gstart[g], e = g_gstart[g + 1];
    int c = threadIdx.x;
    float acc = 0.0f;
    for (int r = s + part; r < e; r += 8)
        acc += g_h[(size_t)r * HH + c] * g_esc[r];
    atomicAdd(&g_pooled[g * HH + c], acc);
}

// ---------------- final MLP ----------------
__global__ void k_mlp(const float* __restrict__ W1, const float* __restrict__ b1,
                      const float* __restrict__ W2, const float* __restrict__ b2,
                      float* __restrict__ out)
{
    __shared__ float p[HH];
    __shared__ float t[HH];
    int g = blockIdx.x, c = threadIdx.x;
    int cnt = g_gstart[g + 1] - g_gstart[g];
    if (cnt < 1) cnt = 1;
    float inv = 1.0f / (g_sumexp * (float)cnt);
    p[c] = g_pooled[g * HH + c] * inv;
    __syncthreads();
    float acc = b1[c];
    for (int k = 0; k < HH; k++) acc += p[k] * W1[k * HH + c];
    t[c] = fmaxf(acc, 0.0f);
    __syncthreads();
    float acc2 = b2[c];
    for (int k = 0; k < HH; k++) acc2 += t[k] * W2[k * HH + c];
    out[g * HH + c] = acc2;
}

// ---------------- host ----------------
extern "C" void kernel_launch(void* const* d_in, const int* in_sizes, int n_in,
                              void* d_out, int out_size)
{
    const float* x      = (const float*)d_in[0];
    const int*   ei     = (const int*)d_in[1];   // [2, E] int32
    const int*   batch  = (const int*)d_in[2];
    const float* conv_w = (const float*)d_in[3];       // [3,128,128]
    const float* conv_b = (const float*)d_in[4];       // [3,128]
    const float* bn_g   = (const float*)d_in[5];
    const float* bn_b   = (const float*)d_in[6];
    const float* aw1    = (const float*)d_in[7];
    const float* ab1    = (const float*)d_in[8];
    const float* aw2    = (const float*)d_in[9];
    const float* ab2    = (const float*)d_in[10];
    const float* pw1    = (const float*)d_in[11];
    const float* pb1    = (const float*)d_in[12];
    const float* pw2    = (const float*)d_in[13];
    const float* pb2    = (const float*)d_in[14];
    float* out = (float*)d_out;

    const int smem = (HH * HH + 2 * BM * LDA) * sizeof(float);   // 200704 B
    cudaFuncSetAttribute(k_gemm, cudaFuncAttributeMaxDynamicSharedMemorySize, smem);

    // degree / norm / CSR build
    k_init <<<(NN + 255) / 256, 256>>>();
    k_count<<<(EE + 255) / 256, 256>>>(ei + EE);
    k_rsqrt<<<(NN + 255) / 256, 256>>>();
    k_scan1<<<SCAN_BLOCKS, 256>>>();
    k_scan2<<<1, 32>>>();
    k_scan3<<<SCAN_BLOCKS, 256>>>();
    k_fill <<<(EE + 255) / 256, 256>>>(ei, ei + EE);

    // 3 GCN layers (separate apply — full-occupancy streaming)
    for (int i = 0; i < 3; i++) {
        const float* A = (i == 0) ? x : nullptr;   // nullptr -> g_h (device-side)
        k_gemm<<<GEMM_GRID, 256, smem>>>(A, conv_w + i * HH * HH, conv_b + i * HH,
                                         nullptr, nullptr, 0);
        k_aggregate<<<AGG_BLOCKS, 256>>>();
        k_bnfin<<<1, 128>>>(bn_g + i * HH, bn_b + i * HH);
        k_apply<<<(NN * 32 + 255) / 256, 256>>>(i > 0 ? 1 : 0);
    }

    // attention GEMM with fused score epilogue
    k_gemm<<<GEMM_GRID, 256, smem>>>(nullptr, aw1, ab1, aw2, ab2, 1);

    // pooling
    k_gstart<<<GG, 128>>>(batch);
    k_pool<<<GG * 8, 128>>>();

    // final MLP
    k_mlp<<<GG, 128>>>(pw1, pb1, pw2, pb2, out);
}

// round 13
// speedup vs baseline: 1.4455x; 1.3589x over previous
#include <cuda_runtime.h>
#include <cuda_bf16.h>
#include <math.h>
#include <stdint.h>

#define NN 100000
#define EE 1600000
#define HH 128
#define GG 64
#define SCAN_BLOCKS 391            // ceil(NN/256)

// ---------------- scratch (device globals; allocation-free) ----------------
__device__ float g_dinv[NN];
__device__ int   g_deg[NN];
__device__ int   g_csr_off[NN + 1];
__device__ int   g_csr_pos[NN];
__device__ int   g_csr_src[EE];
__device__ int   g_part[SCAN_BLOCKS];
__device__ float g_h[NN * HH];
__device__ float g_zs[NN * HH];
__device__ float g_agg[NN * HH];
__device__ float g_sum[HH];
__device__ float g_sumsq[HH];
__device__ float g_scale[HH];
__device__ float g_shift[HH];
__device__ float g_esc[NN];
__device__ float g_sumexp;
__device__ int   g_gstart[GG + 1];
__device__ float g_pooled[GG * HH];

// ---------------- helpers ----------------
__device__ __forceinline__ void cp_async16(float* smem_dst, const float* gsrc) {
    unsigned int s = (unsigned int)__cvta_generic_to_shared(smem_dst);
    asm volatile("cp.async.cg.shared.global [%0], [%1], 16;" :: "r"(s), "l"(gsrc));
}
// pack two f32 -> bf16x2; element for even-k goes to LOW half
static __device__ __forceinline__ uint32_t packbf(float e, float o) {
    uint32_t r;
    asm("cvt.rn.bf16x2.f32 %0, %1, %2;" : "=r"(r) : "f"(o), "f"(e));
    return r;
}
static __device__ __forceinline__ float2 bf2f(uint32_t p) {
    float2 r;
    r.x = __uint_as_float(p << 16);
    r.y = __uint_as_float(p & 0xffff0000u);
    return r;
}
static __device__ __forceinline__ void splitbf(float e, float o,
                                               uint32_t& hi, uint32_t& lo) {
    hi = packbf(e, o);
    float2 hf = bf2f(hi);
    lo = packbf(e - hf.x, o - hf.y);
}
static __device__ __forceinline__ void mma_bf16(float* c, const uint32_t* a,
                                                uint32_t b0, uint32_t b1) {
    asm volatile(
        "mma.sync.aligned.m16n8k16.row.col.f32.bf16.bf16.f32 "
        "{%0,%1,%2,%3}, {%4,%5,%6,%7}, {%8,%9}, {%0,%1,%2,%3};"
        : "+f"(c[0]), "+f"(c[1]), "+f"(c[2]), "+f"(c[3])
        : "r"(a[0]), "r"(a[1]), "r"(a[2]), "r"(a[3]), "r"(b0), "r"(b1));
}

// ---------------- init / degree ----------------
__global__ void k_init() {
    int i = blockIdx.x * blockDim.x + threadIdx.x;
    if (i < NN) g_deg[i] = 0;
    if (i == 0) g_sumexp = 0.0f;
}

__global__ void k_count(const int* __restrict__ edst) {
    int e = blockIdx.x * blockDim.x + threadIdx.x;
    if (e < EE) atomicAdd(&g_deg[edst[e]], 1);
}

__global__ void k_rsqrt() {
    int i = blockIdx.x * blockDim.x + threadIdx.x;
    if (i < NN) g_dinv[i] = rsqrtf((float)g_deg[i] + 1.0f);   // +1 self loop
}

// ---------------- CSR build ----------------
__global__ __launch_bounds__(256) void k_scan1() {
    __shared__ int sh[256];
    int i = blockIdx.x * 256 + threadIdx.x;
    sh[threadIdx.x] = (i < NN) ? g_deg[i] : 0;
    __syncthreads();
    for (int s = 128; s > 0; s >>= 1) {
        if (threadIdx.x < s) sh[threadIdx.x] += sh[threadIdx.x + s];
        __syncthreads();
    }
    if (threadIdx.x == 0) g_part[blockIdx.x] = sh[0];
}

__global__ void k_scan2() {
    if (threadIdx.x == 0) {
        int run = 0;
        for (int b = 0; b < SCAN_BLOCKS; b++) {
            int v = g_part[b];
            g_part[b] = run;
            run += v;
        }
        g_csr_off[NN] = run;    // == EE
    }
}

__global__ __launch_bounds__(256) void k_scan3() {
    __shared__ int sh[256];
    int i = blockIdx.x * 256 + threadIdx.x;
    int v = (i < NN) ? g_deg[i] : 0;
    sh[threadIdx.x] = v;
    __syncthreads();
    for (int s = 1; s < 256; s <<= 1) {
        int t = (threadIdx.x >= s) ? sh[threadIdx.x - s] : 0;
        __syncthreads();
        sh[threadIdx.x] += t;
        __syncthreads();
    }
    if (i < NN) {
        int excl = sh[threadIdx.x] - v + g_part[blockIdx.x];
        g_csr_off[i] = excl;
        g_csr_pos[i] = excl;
    }
}

__global__ __launch_bounds__(256) void k_fill(const int* __restrict__ esrc,
                                              const int* __restrict__ edst) {
    int e = blockIdx.x * blockDim.x + threadIdx.x;
    if (e >= EE) return;
    int d = edst[e];
    int p = atomicAdd(&g_csr_pos[d], 1);
    g_csr_src[p] = esrc[e];
}

// ============================================================================
// GEMM via mma.sync (HMMA, bf16-split 3-term): Z = Ah*Wh + Ah*Wl + Al*Wh
// Persistent grid=148 x 256 threads, cp.async double-buffered f32 A tiles.
// mode 0: g_zs = Z*dinv[row];  g_agg = Z*dinv^2 + bias[c]
// mode 1: g_esc[row] = exp(tanh(Z+bias)·w2 + b2); sum -> g_sumexp
// ============================================================================
#define GEMM_GRID 148
#define BM 128
#define LDA 132
#define WPITCH 68            // b32 pitch per n-row of split-W (136 bf16)

__device__ __forceinline__ void load_tile_async(float* sA, const float* A, int row0) {
#pragma unroll
    for (int t = 0; t < 16; t++) {
        int idx = threadIdx.x + t * 256;       // 0..4095
        int r = idx >> 5, c4 = idx & 31;
        if (row0 + r < NN)
            cp_async16(&sA[r * LDA + c4 * 4], &A[(size_t)(row0 + r) * HH + c4 * 4]);
    }
}

__global__ __launch_bounds__(256) void k_gemm(
    const float* __restrict__ Ain, const float* __restrict__ W,
    const float* __restrict__ bias,
    const float* __restrict__ w2, const float* __restrict__ b2,
    int mode)
{
    const float* A = (Ain == nullptr) ? g_h : Ain;
    extern __shared__ float smdyn[];
    float* sA0 = smdyn;                          // 128*132 f32
    float* sA1 = smdyn + BM * LDA;
    uint32_t* sWh = (uint32_t*)(smdyn + 2 * BM * LDA);   // [n][k2] pitch 68
    uint32_t* sWl = sWh + HH * WPITCH;
    __shared__ float sBias[HH];
    __shared__ float sW2[HH];
    __shared__ float sh_e;

    int tid = threadIdx.x;
    int wid = tid >> 5, lane = tid & 31;
    int g = lane >> 2, tig = lane & 3;
    int wrow = wid * 16;

    if (tid == 0) sh_e = 0.0f;
    if (tid < HH) {
        sBias[tid] = bias[tid];
        sW2[tid] = (mode == 1) ? w2[tid] : 0.0f;
    }
    float b2v = (mode == 1) ? b2[0] : 0.0f;

    // prefetch first A tile
    load_tile_async(sA0, A, blockIdx.x * BM);
    asm volatile("cp.async.commit_group;");

    // split W once: sW*[n][k2] = {W[2k2][n], W[2k2+1][n]} (coalesced gmem reads)
    for (int idx = tid; idx < HH * 64; idx += 256) {
        int k2 = idx >> 7;            // 0..63
        int n  = idx & 127;
        float w0 = W[(2 * k2) * HH + n];
        float w1 = W[(2 * k2 + 1) * HH + n];
        uint32_t hi, lo;
        splitbf(w0, w1, hi, lo);
        sWh[n * WPITCH + k2] = hi;
        sWl[n * WPITCH + k2] = lo;
    }

    const int NT = (NN + BM - 1) / BM;   // 782
    float esum = 0.0f;
    int cur = 0;

    for (int tile = blockIdx.x; tile < NT; tile += GEMM_GRID) {
        float* sA  = cur ? sA1 : sA0;
        float* sAn = cur ? sA0 : sA1;
        int next = tile + GEMM_GRID;
        if (next < NT) {
            load_tile_async(sAn, A, next * BM);
            asm volatile("cp.async.commit_group;");
            asm volatile("cp.async.wait_group 1;");
        } else {
            asm volatile("cp.async.wait_group 0;");
        }
        __syncthreads();   // A tile (and W split on first iter) visible

        int row0 = tile * BM;
        float acc[16][4];
#pragma unroll
        for (int nt = 0; nt < 16; nt++)
#pragma unroll
            for (int j = 0; j < 4; j++) acc[nt][j] = 0.0f;

#pragma unroll 1
        for (int ks = 0; ks < 8; ks++) {
            int k0 = ks * 16;
            // ---- A fragments (f32 smem -> bf16 hi/lo in regs) ----
            float2 x0 = *(float2*)&sA[(wrow + g) * LDA + k0 + tig * 2];
            float2 x1 = *(float2*)&sA[(wrow + g + 8) * LDA + k0 + tig * 2];
            float2 x2 = *(float2*)&sA[(wrow + g) * LDA + k0 + 8 + tig * 2];
            float2 x3 = *(float2*)&sA[(wrow + g + 8) * LDA + k0 + 8 + tig * 2];
            uint32_t ah[4], al[4];
            splitbf(x0.x, x0.y, ah[0], al[0]);
            splitbf(x1.x, x1.y, ah[1], al[1]);
            splitbf(x2.x, x2.y, ah[2], al[2]);
            splitbf(x3.x, x3.y, ah[3], al[3]);

            int kb = ks * 8 + tig;
#pragma unroll
            for (int nt = 0; nt < 16; nt++) {
                const uint32_t* rh = &sWh[(nt * 8 + g) * WPITCH];
                const uint32_t* rl = &sWl[(nt * 8 + g) * WPITCH];
                uint32_t bh0 = rh[kb], bh1 = rh[kb + 4];
                uint32_t bl0 = rl[kb], bl1 = rl[kb + 4];
                mma_bf16(acc[nt], ah, bh0, bh1);   // Ah*Wh
                mma_bf16(acc[nt], ah, bl0, bl1);   // Ah*Wl
                mma_bf16(acc[nt], al, bh0, bh1);   // Al*Wh
            }
        }

        // ---- epilogue ----
        int r0 = row0 + wrow + g;
        int r1 = r0 + 8;
        if (mode == 0) {
            float di0 = (r0 < NN) ? g_dinv[r0] : 0.0f;
            float di1 = (r1 < NN) ? g_dinv[r1] : 0.0f;
            float d20 = di0 * di0, d21 = di1 * di1;
            size_t o0 = (size_t)r0 * HH, o1 = (size_t)r1 * HH;
#pragma unroll
            for (int nt = 0; nt < 16; nt++) {
                int c = nt * 8 + tig * 2;
                float b0 = sBias[c], b1 = sBias[c + 1];
                if (r0 < NN) {
                    *(float2*)&g_zs[o0 + c] =
                        make_float2(acc[nt][0] * di0, acc[nt][1] * di0);
                    *(float2*)&g_agg[o0 + c] =
                        make_float2(acc[nt][0] * d20 + b0, acc[nt][1] * d20 + b1);
                }
                if (r1 < NN) {
                    *(float2*)&g_zs[o1 + c] =
                        make_float2(acc[nt][2] * di1, acc[nt][3] * di1);
                    *(float2*)&g_agg[o1 + c] =
                        make_float2(acc[nt][2] * d21 + b0, acc[nt][3] * d21 + b1);
                }
            }
        } else {
            float p0 = 0.0f, p1 = 0.0f;
#pragma unroll
            for (int nt = 0; nt < 16; nt++) {
                int c = nt * 8 + tig * 2;
                float b0 = sBias[c], b1 = sBias[c + 1];
                float w0 = sW2[c], w1 = sW2[c + 1];
                p0 += tanhf(acc[nt][0] + b0) * w0 + tanhf(acc[nt][1] + b1) * w1;
                p1 += tanhf(acc[nt][2] + b0) * w0 + tanhf(acc[nt][3] + b1) * w1;
            }
            // reduce over tig (4 lanes per row)
            p0 += __shfl_xor_sync(0xffffffffu, p0, 1);
            p0 += __shfl_xor_sync(0xffffffffu, p0, 2);
            p1 += __shfl_xor_sync(0xffffffffu, p1, 1);
            p1 += __shfl_xor_sync(0xffffffffu, p1, 2);
            if (tig == 0) {
                if (r0 < NN) {
                    float e = expf(p0 + b2v);
                    g_esc[r0] = e;
                    esum += e;
                }
                if (r1 < NN) {
                    float e = expf(p1 + b2v);
                    g_esc[r1] = e;
                    esum += e;
                }
            }
        }

        __syncthreads();   // done reading sA before refill
        cur ^= 1;
    }

    if (mode == 1) {
        if (tig == 0) atomicAdd(&sh_e, esum);
        __syncthreads();
        if (tid == 0) atomicAdd(&g_sumexp, sh_e);
    }
}

// ---------------- aggregate (CSR gather) + fused BN stats (FROZEN) --------
#define AGG_BLOCKS 1184
__global__ __launch_bounds__(256) void k_aggregate() {
    int tid = threadIdx.x;
    int lane = tid & 31, warp = tid >> 5;
    int gw = blockIdx.x * 8 + warp;
    int nw = gridDim.x * 8;
    float4 s4 = make_float4(0, 0, 0, 0);
    float4 q4 = make_float4(0, 0, 0, 0);

    for (int node = gw; node < NN; node += nw) {
        int beg = g_csr_off[node], end = g_csr_off[node + 1];
        float4 acc = make_float4(0, 0, 0, 0);
        for (int base = beg; base < end; base += 32) {
            int idx = base + lane;
            int s = (idx < end) ? g_csr_src[idx] : 0;
            int cnt = min(32, end - base);
            for (int j = 0; j < cnt; j++) {
                int ss = __shfl_sync(0xffffffffu, s, j);
                float4 v = *(const float4*)&g_zs[(size_t)ss * HH + lane * 4];
                acc.x += v.x; acc.y += v.y; acc.z += v.z; acc.w += v.w;
            }
        }
        float di = g_dinv[node];
        float* rowp = &g_agg[(size_t)node * HH + lane * 4];
        float4 r = *(float4*)rowp;
        r.x += di * acc.x; r.y += di * acc.y; r.z += di * acc.z; r.w += di * acc.w;
        *(float4*)rowp = r;
        s4.x += r.x; s4.y += r.y; s4.z += r.z; s4.w += r.w;
        q4.x += r.x * r.x; q4.y += r.y * r.y; q4.z += r.z * r.z; q4.w += r.w * r.w;
    }

    __shared__ float sh[8][HH];
    ((float4*)sh[warp])[lane] = s4;
    __syncthreads();
    if (tid < HH) {
        float t = 0.0f;
#pragma unroll
        for (int w = 0; w < 8; w++) t += sh[w][tid];
        atomicAdd(&g_sum[tid], t);
    }
    __syncthreads();
    ((float4*)sh[warp])[lane] = q4;
    __syncthreads();
    if (tid < HH) {
        float t = 0.0f;
#pragma unroll
        for (int w = 0; w < 8; w++) t += sh[w][tid];
        atomicAdd(&g_sumsq[tid], t);
    }
}

// ---------------- batchnorm finalize / apply ----------------
__global__ void k_bnfin(const float* __restrict__ gamma, const float* __restrict__ beta) {
    int c = threadIdx.x;
    float mean = g_sum[c] / (float)NN;
    float var = g_sumsq[c] / (float)NN - mean * mean;
    float sc = rsqrtf(var + 1e-5f) * gamma[c];
    g_scale[c] = sc;
    g_shift[c] = beta[c] - mean * sc;
    g_sum[c] = 0.0f;
    g_sumsq[c] = 0.0f;
}

__global__ __launch_bounds__(256) void k_apply(int residual) {
    int i4 = blockIdx.x * blockDim.x + threadIdx.x;   // over NN*32 float4s
    if (i4 >= NN * 32) return;
    int c4 = i4 & 31;
    float4 v  = ((const float4*)g_agg)[i4];
    float4 sc = ((const float4*)g_scale)[c4];
    float4 sf = ((const float4*)g_shift)[c4];
    float4 r;
    r.x = fmaxf(v.x * sc.x + sf.x, 0.0f);
    r.y = fmaxf(v.y * sc.y + sf.y, 0.0f);
    r.z = fmaxf(v.z * sc.z + sf.z, 0.0f);
    r.w = fmaxf(v.w * sc.w + sf.w, 0.0f);
    if (residual) {
        float4 hv = ((const float4*)g_h)[i4];
        r.x += hv.x; r.y += hv.y; r.z += hv.z; r.w += hv.w;
    }
    ((float4*)g_h)[i4] = r;
}

// ---------------- graph offsets + zero pooled ----------------
__global__ void k_gstart(const int* __restrict__ batch) {
    int g = blockIdx.x, c = threadIdx.x;
    g_pooled[g * HH + c] = 0.0f;
    if (c == 0) {
        int lo = 0, hi = NN;
        while (lo < hi) {
            int m = (lo + hi) >> 1;
            if (batch[m] < g) lo = m + 1; else hi = m;
        }
        g_gstart[g] = lo;
        if (g == 0) g_gstart[GG] = NN;
    }
}

// ---------------- pooling (weighted sums) ----------------
__global__ void k_pool() {
    int g = blockIdx.x >> 3;
    int part = blockIdx.x & 7;
    int s = g_gstart[g], e = g_gstart[g + 1];
    int c = threadIdx.x;
    float acc = 0.0f;
    for (int r = s + part; r < e; r += 8)
        acc += g_h[(size_t)r * HH + c] * g_esc[r];
    atomicAdd(&g_pooled[g * HH + c], acc);
}

// ---------------- final MLP ----------------
__global__ void k_mlp(const float* __restrict__ W1, const float* __restrict__ b1,
                      const float* __restrict__ W2, const float* __restrict__ b2,
                      float* __restrict__ out)
{
    __shared__ float p[HH];
    __shared__ float t[HH];
    int g = blockIdx.x, c = threadIdx.x;
    int cnt = g_gstart[g + 1] - g_gstart[g];
    if (cnt < 1) cnt = 1;
    float inv = 1.0f / (g_sumexp * (float)cnt);
    p[c] = g_pooled[g * HH + c] * inv;
    __syncthreads();
    float acc = b1[c];
    for (int k = 0; k < HH; k++) acc += p[k] * W1[k * HH + c];
    t[c] = fmaxf(acc, 0.0f);
    __syncthreads();
    float acc2 = b2[c];
    for (int k = 0; k < HH; k++) acc2 += t[k] * W2[k * HH + c];
    out[g * HH + c] = acc2;
}

// ---------------- host ----------------
extern "C" void kernel_launch(void* const* d_in, const int* in_sizes, int n_in,
                              void* d_out, int out_size)
{
    const float* x      = (const float*)d_in[0];
    const int*   ei     = (const int*)d_in[1];   // [2, E] int32
    const int*   batch  = (const int*)d_in[2];
    const float* conv_w = (const float*)d_in[3];       // [3,128,128]
    const float* conv_b = (const float*)d_in[4];       // [3,128]
    const float* bn_g   = (const float*)d_in[5];
    const float* bn_b   = (const float*)d_in[6];
    const float* aw1    = (const float*)d_in[7];
    const float* ab1    = (const float*)d_in[8];
    const float* aw2    = (const float*)d_in[9];
    const float* ab2    = (const float*)d_in[10];
    const float* pw1    = (const float*)d_in[11];
    const float* pb1    = (const float*)d_in[12];
    const float* pw2    = (const float*)d_in[13];
    const float* pb2    = (const float*)d_in[14];
    float* out = (float*)d_out;

    // dyn smem: 2 f32 A tiles (2*128*132*4) + 2 split-W (2*128*68*4) = 204800 B
    const int smem = (2 * BM * LDA + 2 * HH * WPITCH) * 4;
    cudaFuncSetAttribute(k_gemm, cudaFuncAttributeMaxDynamicSharedMemorySize, smem);

    // degree / norm / CSR build
    k_init <<<(NN + 255) / 256, 256>>>();
    k_count<<<(EE + 255) / 256, 256>>>(ei + EE);
    k_rsqrt<<<(NN + 255) / 256, 256>>>();
    k_scan1<<<SCAN_BLOCKS, 256>>>();
    k_scan2<<<1, 32>>>();
    k_scan3<<<SCAN_BLOCKS, 256>>>();
    k_fill <<<(EE + 255) / 256, 256>>>(ei, ei + EE);

    // 3 GCN layers
    for (int i = 0; i < 3; i++) {
        const float* A = (i == 0) ? x : nullptr;   // nullptr -> g_h (device-side)
        k_gemm<<<GEMM_GRID, 256, smem>>>(A, conv_w + i * HH * HH, conv_b + i * HH,
                                         nullptr, nullptr, 0);
        k_aggregate<<<AGG_BLOCKS, 256>>>();
        k_bnfin<<<1, 128>>>(bn_g + i * HH, bn_b + i * HH);
        k_apply<<<(NN * 32 + 255) / 256, 256>>>(i > 0 ? 1 : 0);
    }

    // attention GEMM with fused score epilogue
    k_gemm<<<GEMM_GRID, 256, smem>>>(nullptr, aw1, ab1, aw2, ab2, 1);

    // pooling
    k_gstart<<<GG, 128>>>(batch);
    k_pool<<<GG * 8, 128>>>();

    // final MLP
    k_mlp<<<GG, 128>>>(pw1, pb1, pw2, pb2, out);
}

// round 14
// speedup vs baseline: 1.6313x; 1.1286x over previous
#include <cuda_runtime.h>
#include <cuda_bf16.h>
#include <cuda_fp16.h>
#include <math.h>
#include <stdint.h>

#define NN 100000
#define EE 1600000
#define HH 128
#define GG 64
#define SCAN_BLOCKS 391            // ceil(NN/256)

// ---------------- scratch (device globals; allocation-free) ----------------
__device__ float g_dinv[NN];
__device__ int   g_deg[NN];
__device__ int   g_csr_off[NN + 1];
__device__ int   g_csr_pos[NN];
__device__ int   g_csr_src[EE];
__device__ int   g_part[SCAN_BLOCKS];
__device__ float g_h[NN * HH];
__device__ __half g_zs[NN * HH];          // fp16: gather traffic halved
__device__ float g_agg[NN * HH];
__device__ float g_sum[HH];
__device__ float g_sumsq[HH];
__device__ float g_scale[HH];
__device__ float g_shift[HH];
__device__ float g_esc[NN];
__device__ float g_sumexp;
__device__ int   g_gstart[GG + 1];
__device__ float g_pooled[GG * HH];

// ---------------- helpers ----------------
__device__ __forceinline__ void cp_async16(float* smem_dst, const float* gsrc) {
    unsigned int s = (unsigned int)__cvta_generic_to_shared(smem_dst);
    asm volatile("cp.async.cg.shared.global [%0], [%1], 16;" :: "r"(s), "l"(gsrc));
}
// pack two f32 -> bf16x2; element for even-k goes to LOW half
static __device__ __forceinline__ uint32_t packbf(float e, float o) {
    uint32_t r;
    asm("cvt.rn.bf16x2.f32 %0, %1, %2;" : "=r"(r) : "f"(o), "f"(e));
    return r;
}
static __device__ __forceinline__ float2 bf2f(uint32_t p) {
    float2 r;
    r.x = __uint_as_float(p << 16);
    r.y = __uint_as_float(p & 0xffff0000u);
    return r;
}
static __device__ __forceinline__ void splitbf(float e, float o,
                                               uint32_t& hi, uint32_t& lo) {
    hi = packbf(e, o);
    float2 hf = bf2f(hi);
    lo = packbf(e - hf.x, o - hf.y);
}
static __device__ __forceinline__ void mma_bf16(float* c, const uint32_t* a,
                                                uint32_t b0, uint32_t b1) {
    asm volatile(
        "mma.sync.aligned.m16n8k16.row.col.f32.bf16.bf16.f32 "
        "{%0,%1,%2,%3}, {%4,%5,%6,%7}, {%8,%9}, {%0,%1,%2,%3};"
        : "+f"(c[0]), "+f"(c[1]), "+f"(c[2]), "+f"(c[3])
        : "r"(a[0]), "r"(a[1]), "r"(a[2]), "r"(a[3]), "r"(b0), "r"(b1));
}

// ---------------- init / degree ----------------
__global__ void k_init() {
    int i = blockIdx.x * blockDim.x + threadIdx.x;
    if (i < NN) g_deg[i] = 0;
    if (i == 0) g_sumexp = 0.0f;
}

__global__ void k_count(const int* __restrict__ edst) {
    int e = blockIdx.x * blockDim.x + threadIdx.x;
    if (e < EE) atomicAdd(&g_deg[edst[e]], 1);
}

__global__ void k_rsqrt() {
    int i = blockIdx.x * blockDim.x + threadIdx.x;
    if (i < NN) g_dinv[i] = rsqrtf((float)g_deg[i] + 1.0f);   // +1 self loop
}

// ---------------- CSR build ----------------
__global__ __launch_bounds__(256) void k_scan1() {
    __shared__ int sh[256];
    int i = blockIdx.x * 256 + threadIdx.x;
    sh[threadIdx.x] = (i < NN) ? g_deg[i] : 0;
    __syncthreads();
    for (int s = 128; s > 0; s >>= 1) {
        if (threadIdx.x < s) sh[threadIdx.x] += sh[threadIdx.x + s];
        __syncthreads();
    }
    if (threadIdx.x == 0) g_part[blockIdx.x] = sh[0];
}

__global__ void k_scan2() {
    if (threadIdx.x == 0) {
        int run = 0;
        for (int b = 0; b < SCAN_BLOCKS; b++) {
            int v = g_part[b];
            g_part[b] = run;
            run += v;
        }
        g_csr_off[NN] = run;    // == EE
    }
}

__global__ __launch_bounds__(256) void k_scan3() {
    __shared__ int sh[256];
    int i = blockIdx.x * 256 + threadIdx.x;
    int v = (i < NN) ? g_deg[i] : 0;
    sh[threadIdx.x] = v;
    __syncthreads();
    for (int s = 1; s < 256; s <<= 1) {
        int t = (threadIdx.x >= s) ? sh[threadIdx.x - s] : 0;
        __syncthreads();
        sh[threadIdx.x] += t;
        __syncthreads();
    }
    if (i < NN) {
        int excl = sh[threadIdx.x] - v + g_part[blockIdx.x];
        g_csr_off[i] = excl;
        g_csr_pos[i] = excl;
    }
}

__global__ __launch_bounds__(256) void k_fill(const int* __restrict__ esrc,
                                              const int* __restrict__ edst) {
    int e = blockIdx.x * blockDim.x + threadIdx.x;
    if (e >= EE) return;
    int d = edst[e];
    int p = atomicAdd(&g_csr_pos[d], 1);
    g_csr_src[p] = esrc[e];
}

// ============================================================================
// GEMM via mma.sync (HMMA, bf16-split 3-term): Z = Ah*Wh + Ah*Wl + Al*Wh
// Persistent grid=148 x 256 threads, cp.async double-buffered f32 A tiles.
// mode 0: g_zs = fp16(Z*dinv[row]);  g_agg = Z*dinv^2 + bias[c]
// mode 1: g_esc[row] = exp(tanh(Z+bias)·w2 + b2); sum -> g_sumexp
// ============================================================================
#define GEMM_GRID 148
#define BM 128
#define LDA 132
#define WPITCH 68            // b32 pitch per n-row of split-W (136 bf16)

__device__ __forceinline__ void load_tile_async(float* sA, const float* A, int row0) {
#pragma unroll
    for (int t = 0; t < 16; t++) {
        int idx = threadIdx.x + t * 256;       // 0..4095
        int r = idx >> 5, c4 = idx & 31;
        if (row0 + r < NN)
            cp_async16(&sA[r * LDA + c4 * 4], &A[(size_t)(row0 + r) * HH + c4 * 4]);
    }
}

__global__ __launch_bounds__(256) void k_gemm(
    const float* __restrict__ Ain, const float* __restrict__ W,
    const float* __restrict__ bias,
    const float* __restrict__ w2, const float* __restrict__ b2,
    int mode)
{
    const float* A = (Ain == nullptr) ? g_h : Ain;
    extern __shared__ float smdyn[];
    float* sA0 = smdyn;                          // 128*132 f32
    float* sA1 = smdyn + BM * LDA;
    uint32_t* sWh = (uint32_t*)(smdyn + 2 * BM * LDA);   // [n][k2] pitch 68
    uint32_t* sWl = sWh + HH * WPITCH;
    __shared__ float sBias[HH];
    __shared__ float sW2[HH];
    __shared__ float sh_e;

    int tid = threadIdx.x;
    int wid = tid >> 5, lane = tid & 31;
    int g = lane >> 2, tig = lane & 3;
    int wrow = wid * 16;

    if (tid == 0) sh_e = 0.0f;
    if (tid < HH) {
        sBias[tid] = bias[tid];
        sW2[tid] = (mode == 1) ? w2[tid] : 0.0f;
    }
    float b2v = (mode == 1) ? b2[0] : 0.0f;

    // prefetch first A tile
    load_tile_async(sA0, A, blockIdx.x * BM);
    asm volatile("cp.async.commit_group;");

    // split W once: sW*[n][k2] = {W[2k2][n], W[2k2+1][n]} (coalesced gmem reads)
    for (int idx = tid; idx < HH * 64; idx += 256) {
        int k2 = idx >> 7;            // 0..63
        int n  = idx & 127;
        float w0 = W[(2 * k2) * HH + n];
        float w1 = W[(2 * k2 + 1) * HH + n];
        uint32_t hi, lo;
        splitbf(w0, w1, hi, lo);
        sWh[n * WPITCH + k2] = hi;
        sWl[n * WPITCH + k2] = lo;
    }

    const int NT = (NN + BM - 1) / BM;   // 782
    float esum = 0.0f;
    int cur = 0;

    for (int tile = blockIdx.x; tile < NT; tile += GEMM_GRID) {
        float* sA  = cur ? sA1 : sA0;
        float* sAn = cur ? sA0 : sA1;
        int next = tile + GEMM_GRID;
        if (next < NT) {
            load_tile_async(sAn, A, next * BM);
            asm volatile("cp.async.commit_group;");
            asm volatile("cp.async.wait_group 1;");
        } else {
            asm volatile("cp.async.wait_group 0;");
        }
        __syncthreads();   // A tile (and W split on first iter) visible

        int row0 = tile * BM;
        float acc[16][4];
#pragma unroll
        for (int nt = 0; nt < 16; nt++)
#pragma unroll
            for (int j = 0; j < 4; j++) acc[nt][j] = 0.0f;

#pragma unroll 1
        for (int ks = 0; ks < 8; ks++) {
            int k0 = ks * 16;
            // ---- A fragments (f32 smem -> bf16 hi/lo in regs) ----
            float2 x0 = *(float2*)&sA[(wrow + g) * LDA + k0 + tig * 2];
            float2 x1 = *(float2*)&sA[(wrow + g + 8) * LDA + k0 + tig * 2];
            float2 x2 = *(float2*)&sA[(wrow + g) * LDA + k0 + 8 + tig * 2];
            float2 x3 = *(float2*)&sA[(wrow + g + 8) * LDA + k0 + 8 + tig * 2];
            uint32_t ah[4], al[4];
            splitbf(x0.x, x0.y, ah[0], al[0]);
            splitbf(x1.x, x1.y, ah[1], al[1]);
            splitbf(x2.x, x2.y, ah[2], al[2]);
            splitbf(x3.x, x3.y, ah[3], al[3]);

            int kb = ks * 8 + tig;
#pragma unroll
            for (int nt = 0; nt < 16; nt++) {
                const uint32_t* rh = &sWh[(nt * 8 + g) * WPITCH];
                const uint32_t* rl = &sWl[(nt * 8 + g) * WPITCH];
                uint32_t bh0 = rh[kb], bh1 = rh[kb + 4];
                uint32_t bl0 = rl[kb], bl1 = rl[kb + 4];
                mma_bf16(acc[nt], ah, bh0, bh1);   // Ah*Wh
                mma_bf16(acc[nt], ah, bl0, bl1);   // Ah*Wl
                mma_bf16(acc[nt], al, bh0, bh1);   // Al*Wh
            }
        }

        // ---- epilogue ----
        int r0 = row0 + wrow + g;
        int r1 = r0 + 8;
        if (mode == 0) {
            float di0 = (r0 < NN) ? g_dinv[r0] : 0.0f;
            float di1 = (r1 < NN) ? g_dinv[r1] : 0.0f;
            float d20 = di0 * di0, d21 = di1 * di1;
            size_t o0 = (size_t)r0 * HH, o1 = (size_t)r1 * HH;
#pragma unroll
            for (int nt = 0; nt < 16; nt++) {
                int c = nt * 8 + tig * 2;
                float b0 = sBias[c], b1 = sBias[c + 1];
                if (r0 < NN) {
                    *(__half2*)&g_zs[o0 + c] =
                        __floats2half2_rn(acc[nt][0] * di0, acc[nt][1] * di0);
                    *(float2*)&g_agg[o0 + c] =
                        make_float2(acc[nt][0] * d20 + b0, acc[nt][1] * d20 + b1);
                }
                if (r1 < NN) {
                    *(__half2*)&g_zs[o1 + c] =
                        __floats2half2_rn(acc[nt][2] * di1, acc[nt][3] * di1);
                    *(float2*)&g_agg[o1 + c] =
                        make_float2(acc[nt][2] * d21 + b0, acc[nt][3] * d21 + b1);
                }
            }
        } else {
            float p0 = 0.0f, p1 = 0.0f;
#pragma unroll
            for (int nt = 0; nt < 16; nt++) {
                int c = nt * 8 + tig * 2;
                float b0 = sBias[c], b1 = sBias[c + 1];
                float w0 = sW2[c], w1 = sW2[c + 1];
                p0 += tanhf(acc[nt][0] + b0) * w0 + tanhf(acc[nt][1] + b1) * w1;
                p1 += tanhf(acc[nt][2] + b0) * w0 + tanhf(acc[nt][3] + b1) * w1;
            }
            // reduce over tig (4 lanes per row)
            p0 += __shfl_xor_sync(0xffffffffu, p0, 1);
            p0 += __shfl_xor_sync(0xffffffffu, p0, 2);
            p1 += __shfl_xor_sync(0xffffffffu, p1, 1);
            p1 += __shfl_xor_sync(0xffffffffu, p1, 2);
            if (tig == 0) {
                if (r0 < NN) {
                    float e = expf(p0 + b2v);
                    g_esc[r0] = e;
                    esum += e;
                }
                if (r1 < NN) {
                    float e = expf(p1 + b2v);
                    g_esc[r1] = e;
                    esum += e;
                }
            }
        }

        __syncthreads();   // done reading sA before refill
        cur ^= 1;
    }

    if (mode == 1) {
        if (tig == 0) atomicAdd(&sh_e, esum);
        __syncthreads();
        if (tid == 0) atomicAdd(&g_sumexp, sh_e);
    }
}

// ---------------- aggregate (CSR gather, fp16 zs) + fused BN stats --------
#define AGG_BLOCKS 1184
__global__ __launch_bounds__(256) void k_aggregate() {
    int tid = threadIdx.x;
    int lane = tid & 31, warp = tid >> 5;
    int gw = blockIdx.x * 8 + warp;
    int nw = gridDim.x * 8;
    float4 s4 = make_float4(0, 0, 0, 0);
    float4 q4 = make_float4(0, 0, 0, 0);

    for (int node = gw; node < NN; node += nw) {
        int beg = g_csr_off[node], end = g_csr_off[node + 1];
        float4 acc = make_float4(0, 0, 0, 0);
        for (int base = beg; base < end; base += 32) {
            int idx = base + lane;
            int s = (idx < end) ? g_csr_src[idx] : 0;
            int cnt = min(32, end - base);
            for (int j = 0; j < cnt; j++) {
                int ss = __shfl_sync(0xffffffffu, s, j);
                uint2 raw = *(const uint2*)&g_zs[(size_t)ss * HH + lane * 4];
                float2 f0 = __half22float2(*(__half2*)&raw.x);
                float2 f1 = __half22float2(*(__half2*)&raw.y);
                acc.x += f0.x; acc.y += f0.y; acc.z += f1.x; acc.w += f1.y;
            }
        }
        float di = g_dinv[node];
        float* rowp = &g_agg[(size_t)node * HH + lane * 4];
        float4 r = *(float4*)rowp;
        r.x += di * acc.x; r.y += di * acc.y; r.z += di * acc.z; r.w += di * acc.w;
        *(float4*)rowp = r;
        s4.x += r.x; s4.y += r.y; s4.z += r.z; s4.w += r.w;
        q4.x += r.x * r.x; q4.y += r.y * r.y; q4.z += r.z * r.z; q4.w += r.w * r.w;
    }

    __shared__ float sh[8][HH];
    ((float4*)sh[warp])[lane] = s4;
    __syncthreads();
    if (tid < HH) {
        float t = 0.0f;
#pragma unroll
        for (int w = 0; w < 8; w++) t += sh[w][tid];
        atomicAdd(&g_sum[tid], t);
    }
    __syncthreads();
    ((float4*)sh[warp])[lane] = q4;
    __syncthreads();
    if (tid < HH) {
        float t = 0.0f;
#pragma unroll
        for (int w = 0; w < 8; w++) t += sh[w][tid];
        atomicAdd(&g_sumsq[tid], t);
    }
}

// ---------------- batchnorm finalize / apply ----------------
__global__ void k_bnfin(const float* __restrict__ gamma, const float* __restrict__ beta) {
    int c = threadIdx.x;
    float mean = g_sum[c] / (float)NN;
    float var = g_sumsq[c] / (float)NN - mean * mean;
    float sc = rsqrtf(var + 1e-5f) * gamma[c];
    g_scale[c] = sc;
    g_shift[c] = beta[c] - mean * sc;
    g_sum[c] = 0.0f;
    g_sumsq[c] = 0.0f;
}

__global__ __launch_bounds__(256) void k_apply(int residual) {
    int i4 = blockIdx.x * blockDim.x + threadIdx.x;   // over NN*32 float4s
    if (i4 >= NN * 32) return;
    int c4 = i4 & 31;
    float4 v  = ((const float4*)g_agg)[i4];
    float4 sc = ((const float4*)g_scale)[c4];
    float4 sf = ((const float4*)g_shift)[c4];
    float4 r;
    r.x = fmaxf(v.x * sc.x + sf.x, 0.0f);
    r.y = fmaxf(v.y * sc.y + sf.y, 0.0f);
    r.z = fmaxf(v.z * sc.z + sf.z, 0.0f);
    r.w = fmaxf(v.w * sc.w + sf.w, 0.0f);
    if (residual) {
        float4 hv = ((const float4*)g_h)[i4];
        r.x += hv.x; r.y += hv.y; r.z += hv.z; r.w += hv.w;
    }
    ((float4*)g_h)[i4] = r;
}

// ---------------- graph offsets + zero pooled ----------------
__global__ void k_gstart(const int* __restrict__ batch) {
    int g = blockIdx.x, c = threadIdx.x;
    g_pooled[g * HH + c] = 0.0f;
    if (c == 0) {
        int lo = 0, hi = NN;
        while (lo < hi) {
            int m = (lo + hi) >> 1;
            if (batch[m] < g) lo = m + 1; else hi = m;
        }
        g_gstart[g] = lo;
        if (g == 0) g_gstart[GG] = NN;
    }
}

// ---------------- pooling (weighted sums) ----------------
__global__ void k_pool() {
    int g = blockIdx.x >> 3;
    int part = blockIdx.x & 7;
    int s = g_gstart[g], e = g_gstart[g + 1];
    int c = threadIdx.x;
    float acc = 0.0f;
    for (int r = s + part; r < e; r += 8)
        acc += g_h[(size_t)r * HH + c] * g_esc[r];
    atomicAdd(&g_pooled[g * HH + c], acc);
}

// ---------------- final MLP ----------------
__global__ void k_mlp(const float* __restrict__ W1, const float* __restrict__ b1,
                      const float* __restrict__ W2, const float* __restrict__ b2,
                      float* __restrict__ out)
{
    __shared__ float p[HH];
    __shared__ float t[HH];
    int g = blockIdx.x, c = threadIdx.x;
    int cnt = g_gstart[g + 1] - g_gstart[g];
    if (cnt < 1) cnt = 1;
    float inv = 1.0f / (g_sumexp * (float)cnt);
    p[c] = g_pooled[g * HH + c] * inv;
    __syncthreads();
    float acc = b1[c];
    for (int k = 0; k < HH; k++) acc += p[k] * W1[k * HH + c];
    t[c] = fmaxf(acc, 0.0f);
    __syncthreads();
    float acc2 = b2[c];
    for (int k = 0; k < HH; k++) acc2 += t[k] * W2[k * HH + c];
    out[g * HH + c] = acc2;
}

// ---------------- host ----------------
extern "C" void kernel_launch(void* const* d_in, const int* in_sizes, int n_in,
                              void* d_out, int out_size)
{
    const float* x      = (const float*)d_in[0];
    const int*   ei     = (const int*)d_in[1];   // [2, E] int32
    const int*   batch  = (const int*)d_in[2];
    const float* conv_w = (const float*)d_in[3];       // [3,128,128]
    const float* conv_b = (const float*)d_in[4];       // [3,128]
    const float* bn_g   = (const float*)d_in[5];
    const float* bn_b   = (const float*)d_in[6];
    const float* aw1    = (const float*)d_in[7];
    const float* ab1    = (const float*)d_in[8];
    const float* aw2    = (const float*)d_in[9];
    const float* ab2    = (const float*)d_in[10];
    const float* pw1    = (const float*)d_in[11];
    const float* pb1    = (const float*)d_in[12];
    const float* pw2    = (const float*)d_in[13];
    const float* pb2    = (const float*)d_in[14];
    float* out = (float*)d_out;

    // dyn smem: 2 f32 A tiles (2*128*132*4) + 2 split-W (2*128*68*4) = 204800 B
    const int smem = (2 * BM * LDA + 2 * HH * WPITCH) * 4;
    cudaFuncSetAttribute(k_gemm, cudaFuncAttributeMaxDynamicSharedMemorySize, smem);

    // degree / norm / CSR build
    k_init <<<(NN + 255) / 256, 256>>>();
    k_count<<<(EE + 255) / 256, 256>>>(ei + EE);
    k_rsqrt<<<(NN + 255) / 256, 256>>>();
    k_scan1<<<SCAN_BLOCKS, 256>>>();
    k_scan2<<<1, 32>>>();
    k_scan3<<<SCAN_BLOCKS, 256>>>();
    k_fill <<<(EE + 255) / 256, 256>>>(ei, ei + EE);

    // 3 GCN layers
    for (int i = 0; i < 3; i++) {
        const float* A = (i == 0) ? x : nullptr;   // nullptr -> g_h (device-side)
        k_gemm<<<GEMM_GRID, 256, smem>>>(A, conv_w + i * HH * HH, conv_b + i * HH,
                                         nullptr, nullptr, 0);
        k_aggregate<<<AGG_BLOCKS, 256>>>();
        k_bnfin<<<1, 128>>>(bn_g + i * HH, bn_b + i * HH);
        k_apply<<<(NN * 32 + 255) / 256, 256>>>(i > 0 ? 1 : 0);
    }

    // attention GEMM with fused score epilogue
    k_gemm<<<GEMM_GRID, 256, smem>>>(nullptr, aw1, ab1, aw2, ab2, 1);

    // pooling
    k_gstart<<<GG, 128>>>(batch);
    k_pool<<<GG * 8, 128>>>();

    // final MLP
    k_mlp<<<GG, 128>>>(pw1, pb1, pw2, pb2, out);
}

// round 15
// speedup vs baseline: 1.7638x; 1.0813x over previous
#include <cuda_runtime.h>
#include <cuda_bf16.h>
#include <cuda_fp16.h>
#include <math.h>
#include <stdint.h>

#define NN 100000
#define EE 1600000
#define HH 128
#define GG 64
#define SCAN_BLOCKS 391            // ceil(NN/256)

// ---------------- scratch (device globals; allocation-free) ----------------
__device__ float g_dinv[NN];
__device__ int   g_deg[NN];
__device__ int   g_csr_off[NN + 1];
__device__ int   g_csr_pos[NN];
__device__ int   g_csr_src[EE];
__device__ int   g_part[SCAN_BLOCKS];
__device__ __half g_h[NN * HH];           // fp16 h (halved traffic)
__device__ __half g_zs[NN * HH];          // fp16 zs (halved gather traffic)
__device__ float g_agg[NN * HH];
__device__ float g_sum[HH];
__device__ float g_sumsq[HH];
__device__ float g_scale[HH];
__device__ float g_shift[HH];
__device__ float g_esc[NN];
__device__ float g_sumexp;
__device__ int   g_gstart[GG + 1];
__device__ float g_pooled[GG * HH];

// ---------------- helpers ----------------
__device__ __forceinline__ void cp_async16(void* smem_dst, const void* gsrc) {
    unsigned int s = (unsigned int)__cvta_generic_to_shared(smem_dst);
    asm volatile("cp.async.cg.shared.global [%0], [%1], 16;" :: "r"(s), "l"(gsrc));
}
// pack two f32 -> bf16x2; element for even-k goes to LOW half
static __device__ __forceinline__ uint32_t packbf(float e, float o) {
    uint32_t r;
    asm("cvt.rn.bf16x2.f32 %0, %1, %2;" : "=r"(r) : "f"(o), "f"(e));
    return r;
}
static __device__ __forceinline__ float2 bf2f(uint32_t p) {
    float2 r;
    r.x = __uint_as_float(p << 16);
    r.y = __uint_as_float(p & 0xffff0000u);
    return r;
}
static __device__ __forceinline__ void splitbf(float e, float o,
                                               uint32_t& hi, uint32_t& lo) {
    hi = packbf(e, o);
    float2 hf = bf2f(hi);
    lo = packbf(e - hf.x, o - hf.y);
}
static __device__ __forceinline__ void mma_bf16(float* c, const uint32_t* a,
                                                uint32_t b0, uint32_t b1) {
    asm volatile(
        "mma.sync.aligned.m16n8k16.row.col.f32.bf16.bf16.f32 "
        "{%0,%1,%2,%3}, {%4,%5,%6,%7}, {%8,%9}, {%0,%1,%2,%3};"
        : "+f"(c[0]), "+f"(c[1]), "+f"(c[2]), "+f"(c[3])
        : "r"(a[0]), "r"(a[1]), "r"(a[2]), "r"(a[3]), "r"(b0), "r"(b1));
}

// ---------------- init / degree ----------------
__global__ void k_init() {
    int i = blockIdx.x * blockDim.x + threadIdx.x;
    if (i < NN) g_deg[i] = 0;
    if (i == 0) g_sumexp = 0.0f;
}

__global__ void k_count(const int* __restrict__ edst) {
    int e = blockIdx.x * blockDim.x + threadIdx.x;
    if (e < EE) atomicAdd(&g_deg[edst[e]], 1);
}

// ---------------- CSR build ----------------
__global__ __launch_bounds__(256) void k_scan1() {
    __shared__ int sh[256];
    int i = blockIdx.x * 256 + threadIdx.x;
    sh[threadIdx.x] = (i < NN) ? g_deg[i] : 0;
    __syncthreads();
    for (int s = 128; s > 0; s >>= 1) {
        if (threadIdx.x < s) sh[threadIdx.x] += sh[threadIdx.x + s];
        __syncthreads();
    }
    if (threadIdx.x == 0) g_part[blockIdx.x] = sh[0];
}

// parallel scan over SCAN_BLOCKS partials (single 512-thread block)
__global__ __launch_bounds__(512) void k_scan2() {
    __shared__ int sh[512];
    int t = threadIdx.x;
    int v = (t < SCAN_BLOCKS) ? g_part[t] : 0;
    sh[t] = v;
    __syncthreads();
    for (int s = 1; s < 512; s <<= 1) {
        int u = (t >= s) ? sh[t - s] : 0;
        __syncthreads();
        sh[t] += u;
        __syncthreads();
    }
    if (t < SCAN_BLOCKS) g_part[t] = sh[t] - v;   // exclusive
    if (t == 511) g_csr_off[NN] = sh[511];        // total == EE
}

// block scan + offsets + dinv (rsqrt merged here)
__global__ __launch_bounds__(256) void k_scan3() {
    __shared__ int sh[256];
    int i = blockIdx.x * 256 + threadIdx.x;
    int v = (i < NN) ? g_deg[i] : 0;
    sh[threadIdx.x] = v;
    __syncthreads();
    for (int s = 1; s < 256; s <<= 1) {
        int t = (threadIdx.x >= s) ? sh[threadIdx.x - s] : 0;
        __syncthreads();
        sh[threadIdx.x] += t;
        __syncthreads();
    }
    if (i < NN) {
        int excl = sh[threadIdx.x] - v + g_part[blockIdx.x];
        g_csr_off[i] = excl;
        g_csr_pos[i] = excl;
        g_dinv[i] = rsqrtf((float)v + 1.0f);   // +1 self loop
    }
}

__global__ __launch_bounds__(256) void k_fill(const int* __restrict__ esrc,
                                              const int* __restrict__ edst) {
    int e = blockIdx.x * blockDim.x + threadIdx.x;
    if (e >= EE) return;
    int d = edst[e];
    int p = atomicAdd(&g_csr_pos[d], 1);
    g_csr_src[p] = esrc[e];
}

// ============================================================================
// GEMM via mma.sync (HMMA, bf16-split 3-term): Z = Ah*Wh + Ah*Wl + Al*Wh
// Persistent grid=148 x 256 threads, cp.async double-buffered A tiles.
// Templated on A dtype: float (layer 1, reads x) or __half (reads g_h).
// mode 0: g_zs = fp16(Z*dinv[row]);  g_agg = Z*dinv^2 + bias[c]
// mode 1: g_esc[row] = exp(tanh(Z+bias)·w2 + b2); sum -> g_sumexp
// ============================================================================
#define GEMM_GRID 148
#define BM 128
#define LDA 132              // f32 tile pitch (floats)
#define LDAH 136             // fp16 tile pitch (halfs) — 272B, 16B-divisible
#define WPITCH 68            // b32 pitch per n-row of split-W (136 bf16)

__device__ __forceinline__ void load_tile_async(float* sA, const float* A, int row0) {
#pragma unroll
    for (int t = 0; t < 16; t++) {
        int idx = threadIdx.x + t * 256;       // 0..4095 (float4 chunks)
        int r = idx >> 5, c4 = idx & 31;
        if (row0 + r < NN)
            cp_async16(&sA[r * LDA + c4 * 4], &A[(size_t)(row0 + r) * HH + c4 * 4]);
    }
}
__device__ __forceinline__ void load_tile_async(__half* sA, const __half* A, int row0) {
#pragma unroll
    for (int t = 0; t < 8; t++) {
        int idx = threadIdx.x + t * 256;       // 0..2047 (8-half chunks)
        int r = idx >> 4, c8 = idx & 15;
        if (row0 + r < NN)
            cp_async16(&sA[r * LDAH + c8 * 8], &A[(size_t)(row0 + r) * HH + c8 * 8]);
    }
}
__device__ __forceinline__ float2 ldA(const float* sA, int r, int k) {
    return *(const float2*)&sA[r * LDA + k];
}
__device__ __forceinline__ float2 ldA(const __half* sA, int r, int k) {
    return __half22float2(*(const __half2*)&sA[r * LDAH + k]);
}

template <typename AT>
__global__ __launch_bounds__(256) void k_gemm(
    const AT* __restrict__ A, const float* __restrict__ W,
    const float* __restrict__ bias,
    const float* __restrict__ w2, const float* __restrict__ b2,
    int mode)
{
    extern __shared__ float smdyn[];
    AT* sA0 = (AT*)smdyn;
    AT* sA1 = sA0 + BM * (sizeof(AT) == 2 ? LDAH : LDA);
    // W always at fixed byte offset (max of both layouts)
    uint32_t* sWh = (uint32_t*)((char*)smdyn + 2 * BM * LDA * 4);
    uint32_t* sWl = sWh + HH * WPITCH;
    __shared__ float sBias[HH];
    __shared__ float sW2[HH];
    __shared__ float sh_e;

    int tid = threadIdx.x;
    int wid = tid >> 5, lane = tid & 31;
    int g = lane >> 2, tig = lane & 3;
    int wrow = wid * 16;

    if (tid == 0) sh_e = 0.0f;
    if (tid < HH) {
        sBias[tid] = bias[tid];
        sW2[tid] = (mode == 1) ? w2[tid] : 0.0f;
    }
    float b2v = (mode == 1) ? b2[0] : 0.0f;

    // prefetch first A tile
    load_tile_async(sA0, A, blockIdx.x * BM);
    asm volatile("cp.async.commit_group;");

    // split W once: sW*[n][k2] = {W[2k2][n], W[2k2+1][n]}
    for (int idx = tid; idx < HH * 64; idx += 256) {
        int k2 = idx >> 7;            // 0..63
        int n  = idx & 127;
        float w0 = W[(2 * k2) * HH + n];
        float w1 = W[(2 * k2 + 1) * HH + n];
        uint32_t hi, lo;
        splitbf(w0, w1, hi, lo);
        sWh[n * WPITCH + k2] = hi;
        sWl[n * WPITCH + k2] = lo;
    }

    const int NT = (NN + BM - 1) / BM;   // 782
    float esum = 0.0f;
    int cur = 0;

    for (int tile = blockIdx.x; tile < NT; tile += GEMM_GRID) {
        AT* sA  = cur ? sA1 : sA0;
        AT* sAn = cur ? sA0 : sA1;
        int next = tile + GEMM_GRID;
        if (next < NT) {
            load_tile_async(sAn, A, next * BM);
            asm volatile("cp.async.commit_group;");
            asm volatile("cp.async.wait_group 1;");
        } else {
            asm volatile("cp.async.wait_group 0;");
        }
        __syncthreads();   // A tile (and W split on first iter) visible

        int row0 = tile * BM;
        float acc[16][4];
#pragma unroll
        for (int nt = 0; nt < 16; nt++)
#pragma unroll
            for (int j = 0; j < 4; j++) acc[nt][j] = 0.0f;

#pragma unroll 1
        for (int ks = 0; ks < 8; ks++) {
            int k0 = ks * 16;
            float2 x0 = ldA(sA, wrow + g,     k0 + tig * 2);
            float2 x1 = ldA(sA, wrow + g + 8, k0 + tig * 2);
            float2 x2 = ldA(sA, wrow + g,     k0 + 8 + tig * 2);
            float2 x3 = ldA(sA, wrow + g + 8, k0 + 8 + tig * 2);
            uint32_t ah[4], al[4];
            splitbf(x0.x, x0.y, ah[0], al[0]);
            splitbf(x1.x, x1.y, ah[1], al[1]);
            splitbf(x2.x, x2.y, ah[2], al[2]);
            splitbf(x3.x, x3.y, ah[3], al[3]);

            int kb = ks * 8 + tig;
#pragma unroll
            for (int nt = 0; nt < 16; nt++) {
                const uint32_t* rh = &sWh[(nt * 8 + g) * WPITCH];
                const uint32_t* rl = &sWl[(nt * 8 + g) * WPITCH];
                uint32_t bh0 = rh[kb], bh1 = rh[kb + 4];
                uint32_t bl0 = rl[kb], bl1 = rl[kb + 4];
                mma_bf16(acc[nt], ah, bh0, bh1);   // Ah*Wh
                mma_bf16(acc[nt], ah, bl0, bl1);   // Ah*Wl
                mma_bf16(acc[nt], al, bh0, bh1);   // Al*Wh
            }
        }

        // ---- epilogue ----
        int r0 = row0 + wrow + g;
        int r1 = r0 + 8;
        if (mode == 0) {
            float di0 = (r0 < NN) ? g_dinv[r0] : 0.0f;
            float di1 = (r1 < NN) ? g_dinv[r1] : 0.0f;
            float d20 = di0 * di0, d21 = di1 * di1;
            size_t o0 = (size_t)r0 * HH, o1 = (size_t)r1 * HH;
#pragma unroll
            for (int nt = 0; nt < 16; nt++) {
                int c = nt * 8 + tig * 2;
                float b0 = sBias[c], b1 = sBias[c + 1];
                if (r0 < NN) {
                    *(__half2*)&g_zs[o0 + c] =
                        __floats2half2_rn(acc[nt][0] * di0, acc[nt][1] * di0);
                    *(float2*)&g_agg[o0 + c] =
                        make_float2(acc[nt][0] * d20 + b0, acc[nt][1] * d20 + b1);
                }
                if (r1 < NN) {
                    *(__half2*)&g_zs[o1 + c] =
                        __floats2half2_rn(acc[nt][2] * di1, acc[nt][3] * di1);
                    *(float2*)&g_agg[o1 + c] =
                        make_float2(acc[nt][2] * d21 + b0, acc[nt][3] * d21 + b1);
                }
            }
        } else {
            float p0 = 0.0f, p1 = 0.0f;
#pragma unroll
            for (int nt = 0; nt < 16; nt++) {
                int c = nt * 8 + tig * 2;
                float b0 = sBias[c], b1 = sBias[c + 1];
                float w0 = sW2[c], w1 = sW2[c + 1];
                p0 += tanhf(acc[nt][0] + b0) * w0 + tanhf(acc[nt][1] + b1) * w1;
                p1 += tanhf(acc[nt][2] + b0) * w0 + tanhf(acc[nt][3] + b1) * w1;
            }
            p0 += __shfl_xor_sync(0xffffffffu, p0, 1);
            p0 += __shfl_xor_sync(0xffffffffu, p0, 2);
            p1 += __shfl_xor_sync(0xffffffffu, p1, 1);
            p1 += __shfl_xor_sync(0xffffffffu, p1, 2);
            if (tig == 0) {
                if (r0 < NN) {
                    float e = expf(p0 + b2v);
                    g_esc[r0] = e;
                    esum += e;
                }
                if (r1 < NN) {
                    float e = expf(p1 + b2v);
                    g_esc[r1] = e;
                    esum += e;
                }
            }
        }

        __syncthreads();   // done reading sA before refill
        cur ^= 1;
    }

    if (mode == 1) {
        if (tig == 0) atomicAdd(&sh_e, esum);
        __syncthreads();
        if (tid == 0) atomicAdd(&g_sumexp, sh_e);
    }
}

// ---------------- aggregate (CSR gather, fp16 zs) + fused BN stats --------
#define AGG_BLOCKS 1184
__global__ __launch_bounds__(256) void k_aggregate() {
    int tid = threadIdx.x;
    int lane = tid & 31, warp = tid >> 5;
    int gw = blockIdx.x * 8 + warp;
    int nw = gridDim.x * 8;
    float4 s4 = make_float4(0, 0, 0, 0);
    float4 q4 = make_float4(0, 0, 0, 0);

    for (int node = gw; node < NN; node += nw) {
        int beg = g_csr_off[node], end = g_csr_off[node + 1];
        float4 acc = make_float4(0, 0, 0, 0);
        for (int base = beg; base < end; base += 32) {
            int idx = base + lane;
            int s = (idx < end) ? g_csr_src[idx] : 0;
            int cnt = min(32, end - base);
            for (int j = 0; j < cnt; j++) {
                int ss = __shfl_sync(0xffffffffu, s, j);
                uint2 raw = *(const uint2*)&g_zs[(size_t)ss * HH + lane * 4];
                float2 f0 = __half22float2(*(__half2*)&raw.x);
                float2 f1 = __half22float2(*(__half2*)&raw.y);
                acc.x += f0.x; acc.y += f0.y; acc.z += f1.x; acc.w += f1.y;
            }
        }
        float di = g_dinv[node];
        float* rowp = &g_agg[(size_t)node * HH + lane * 4];
        float4 r = *(float4*)rowp;
        r.x += di * acc.x; r.y += di * acc.y; r.z += di * acc.z; r.w += di * acc.w;
        *(float4*)rowp = r;
        s4.x += r.x; s4.y += r.y; s4.z += r.z; s4.w += r.w;
        q4.x += r.x * r.x; q4.y += r.y * r.y; q4.z += r.z * r.z; q4.w += r.w * r.w;
    }

    __shared__ float sh[8][HH];
    ((float4*)sh[warp])[lane] = s4;
    __syncthreads();
    if (tid < HH) {
        float t = 0.0f;
#pragma unroll
        for (int w = 0; w < 8; w++) t += sh[w][tid];
        atomicAdd(&g_sum[tid], t);
    }
    __syncthreads();
    ((float4*)sh[warp])[lane] = q4;
    __syncthreads();
    if (tid < HH) {
        float t = 0.0f;
#pragma unroll
        for (int w = 0; w < 8; w++) t += sh[w][tid];
        atomicAdd(&g_sumsq[tid], t);
    }
}

// ---------------- batchnorm finalize / apply ----------------
__global__ void k_bnfin(const float* __restrict__ gamma, const float* __restrict__ beta) {
    int c = threadIdx.x;
    float mean = g_sum[c] / (float)NN;
    float var = g_sumsq[c] / (float)NN - mean * mean;
    float sc = rsqrtf(var + 1e-5f) * gamma[c];
    g_scale[c] = sc;
    g_shift[c] = beta[c] - mean * sc;
    g_sum[c] = 0.0f;
    g_sumsq[c] = 0.0f;
}

__global__ __launch_bounds__(256) void k_apply(int residual) {
    int i4 = blockIdx.x * blockDim.x + threadIdx.x;   // over NN*32 4-elem chunks
    if (i4 >= NN * 32) return;
    int c4 = i4 & 31;
    float4 v  = ((const float4*)g_agg)[i4];
    float4 sc = ((const float4*)g_scale)[c4];
    float4 sf = ((const float4*)g_shift)[c4];
    float4 r;
    r.x = fmaxf(v.x * sc.x + sf.x, 0.0f);
    r.y = fmaxf(v.y * sc.y + sf.y, 0.0f);
    r.z = fmaxf(v.z * sc.z + sf.z, 0.0f);
    r.w = fmaxf(v.w * sc.w + sf.w, 0.0f);
    if (residual) {
        uint2 raw = *(const uint2*)&g_h[(size_t)i4 * 4];
        float2 f0 = __half22float2(*(__half2*)&raw.x);
        float2 f1 = __half22float2(*(__half2*)&raw.y);
        r.x += f0.x; r.y += f0.y; r.z += f1.x; r.w += f1.y;
    }
    __half2 h0 = __floats2half2_rn(r.x, r.y);
    __half2 h1 = __floats2half2_rn(r.z, r.w);
    uint2 pack;
    pack.x = *(uint32_t*)&h0;
    pack.y = *(uint32_t*)&h1;
    *(uint2*)&g_h[(size_t)i4 * 4] = pack;
}

// ---------------- graph offsets + zero pooled ----------------
__global__ void k_gstart(const int* __restrict__ batch) {
    int g = blockIdx.x, c = threadIdx.x;
    g_pooled[g * HH + c] = 0.0f;
    if (c == 0) {
        int lo = 0, hi = NN;
        while (lo < hi) {
            int m = (lo + hi) >> 1;
            if (batch[m] < g) lo = m + 1; else hi = m;
        }
        g_gstart[g] = lo;
        if (g == 0) g_gstart[GG] = NN;
    }
}

// ---------------- pooling (weighted sums, fp16 h) ----------------
__global__ void k_pool() {
    int g = blockIdx.x >> 3;
    int part = blockIdx.x & 7;
    int s = g_gstart[g], e = g_gstart[g + 1];
    int c = threadIdx.x;
    float acc = 0.0f;
    for (int r = s + part; r < e; r += 8)
        acc += __half2float(g_h[(size_t)r * HH + c]) * g_esc[r];
    atomicAdd(&g_pooled[g * HH + c], acc);
}

// ---------------- final MLP ----------------
__global__ void k_mlp(const float* __restrict__ W1, const float* __restrict__ b1,
                      const float* __restrict__ W2, const float* __restrict__ b2,
                      float* __restrict__ out)
{
    __shared__ float p[HH];
    __shared__ float t[HH];
    int g = blockIdx.x, c = threadIdx.x;
    int cnt = g_gstart[g + 1] - g_gstart[g];
    if (cnt < 1) cnt = 1;
    float inv = 1.0f / (g_sumexp * (float)cnt);
    p[c] = g_pooled[g * HH + c] * inv;
    __syncthreads();
    float acc = b1[c];
    for (int k = 0; k < HH; k++) acc += p[k] * W1[k * HH + c];
    t[c] = fmaxf(acc, 0.0f);
    __syncthreads();
    float acc2 = b2[c];
    for (int k = 0; k < HH; k++) acc2 += t[k] * W2[k * HH + c];
    out[g * HH + c] = acc2;
}

// ---------------- host ----------------
extern "C" void kernel_launch(void* const* d_in, const int* in_sizes, int n_in,
                              void* d_out, int out_size)
{
    const float* x      = (const float*)d_in[0];
    const int*   ei     = (const int*)d_in[1];   // [2, E] int32
    const int*   batch  = (const int*)d_in[2];
    const float* conv_w = (const float*)d_in[3];       // [3,128,128]
    const float* conv_b = (const float*)d_in[4];       // [3,128]
    const float* bn_g   = (const float*)d_in[5];
    const float* bn_b   = (const float*)d_in[6];
    const float* aw1    = (const float*)d_in[7];
    const float* ab1    = (const float*)d_in[8];
    const float* aw2    = (const float*)d_in[9];
    const float* ab2    = (const float*)d_in[10];
    const float* pw1    = (const float*)d_in[11];
    const float* pb1    = (const float*)d_in[12];
    const float* pw2    = (const float*)d_in[13];
    const float* pb2    = (const float*)d_in[14];
    float* out = (float*)d_out;

    // dyn smem: 2 f32 A tiles (2*128*132*4 = 135168) + 2 split-W (2*128*68*4 = 69632)
    const int smem = (2 * BM * LDA + 2 * HH * WPITCH) * 4;   // 204800 B
    cudaFuncSetAttribute(k_gemm<float>,  cudaFuncAttributeMaxDynamicSharedMemorySize, smem);
    cudaFuncSetAttribute(k_gemm<__half>, cudaFuncAttributeMaxDynamicSharedMemorySize, smem);

    // fetch device pointer for g_h (template arg needs a real pointer)
    // NOTE: use cudaGetSymbolAddress (host API, no allocation) — graph-safe.
    static __half* hptr = nullptr;
    if (hptr == nullptr) {
        void* p;
        cudaGetSymbolAddress(&p, g_h);
        hptr = (__half*)p;
    }

    // degree / norm / CSR build
    k_init <<<(NN + 255) / 256, 256>>>();
    k_count<<<(EE + 255) / 256, 256>>>(ei + EE);
    k_scan1<<<SCAN_BLOCKS, 256>>>();
    k_scan2<<<1, 512>>>();
    k_scan3<<<SCAN_BLOCKS, 256>>>();
    k_fill <<<(EE + 255) / 256, 256>>>(ei, ei + EE);

    // layer 1 (A = x, f32)
    k_gemm<float><<<GEMM_GRID, 256, smem>>>(x, conv_w, conv_b, nullptr, nullptr, 0);
    k_aggregate<<<AGG_BLOCKS, 256>>>();
    k_bnfin<<<1, 128>>>(bn_g, bn_b);
    k_apply<<<(NN * 32 + 255) / 256, 256>>>(0);

    // layers 2,3 (A = g_h, fp16)
    for (int i = 1; i < 3; i++) {
        k_gemm<__half><<<GEMM_GRID, 256, smem>>>(hptr, conv_w + i * HH * HH,
                                                 conv_b + i * HH, nullptr, nullptr, 0);
        k_aggregate<<<AGG_BLOCKS, 256>>>();
        k_bnfin<<<1, 128>>>(bn_g + i * HH, bn_b + i * HH);
        k_apply<<<(NN * 32 + 255) / 256, 256>>>(1);
    }

    // attention GEMM (A = g_h fp16) with fused score epilogue
    k_gemm<__half><<<GEMM_GRID, 256, smem>>>(hptr, aw1, ab1, aw2, ab2, 1);

    // pooling
    k_gstart<<<GG, 128>>>(batch);
    k_pool<<<GG * 8, 128>>>();

    // final MLP
    k_mlp<<<GG, 128>>>(pw1, pb1, pw2, pb2, out);
}

// round 16
// speedup vs baseline: 1.8081x; 1.0251x over previous
#include <cuda_runtime.h>
#include <cuda_bf16.h>
#include <cuda_fp16.h>
#include <math.h>
#include <stdint.h>

#define NN 100000
#define EE 1600000
#define HH 128
#define GG 64
#define SCAN_BLOCKS 391            // ceil(NN/256)

// ---------------- scratch (device globals; allocation-free) ----------------
__device__ float g_dinv[NN];
__device__ int   g_deg[NN];
__device__ int   g_csr_off[NN + 1];
__device__ int   g_csr_pos[NN];
__device__ int   g_csr_src[EE];
__device__ int   g_part[SCAN_BLOCKS];
__device__ __half g_h[NN * HH];           // fp16 h
__device__ __half g_zs[NN * HH];          // fp16 zs
__device__ float g_agg[NN * HH];
__device__ float g_sum[HH];
__device__ float g_sumsq[HH];
__device__ float g_scale[HH];
__device__ float g_shift[HH];
__device__ float g_esc[NN];
__device__ float g_sumexp;
__device__ int   g_gstart[GG + 1];
__device__ float g_pooled[GG * HH];

// ---------------- helpers ----------------
__device__ __forceinline__ void cp_async16(void* smem_dst, const void* gsrc) {
    unsigned int s = (unsigned int)__cvta_generic_to_shared(smem_dst);
    asm volatile("cp.async.cg.shared.global [%0], [%1], 16;" :: "r"(s), "l"(gsrc));
}
static __device__ __forceinline__ uint32_t packbf(float e, float o) {
    uint32_t r;
    asm("cvt.rn.bf16x2.f32 %0, %1, %2;" : "=r"(r) : "f"(o), "f"(e));
    return r;
}
static __device__ __forceinline__ float2 bf2f(uint32_t p) {
    float2 r;
    r.x = __uint_as_float(p << 16);
    r.y = __uint_as_float(p & 0xffff0000u);
    return r;
}
static __device__ __forceinline__ void splitbf(float e, float o,
                                               uint32_t& hi, uint32_t& lo) {
    hi = packbf(e, o);
    float2 hf = bf2f(hi);
    lo = packbf(e - hf.x, o - hf.y);
}
static __device__ __forceinline__ void mma_bf16(float* c, const uint32_t* a,
                                                uint32_t b0, uint32_t b1) {
    asm volatile(
        "mma.sync.aligned.m16n8k16.row.col.f32.bf16.bf16.f32 "
        "{%0,%1,%2,%3}, {%4,%5,%6,%7}, {%8,%9}, {%0,%1,%2,%3};"
        : "+f"(c[0]), "+f"(c[1]), "+f"(c[2]), "+f"(c[3])
        : "r"(a[0]), "r"(a[1]), "r"(a[2]), "r"(a[3]), "r"(b0), "r"(b1));
}

// ---------------- init / degree ----------------
__global__ void k_init() {
    int i = blockIdx.x * blockDim.x + threadIdx.x;
    if (i < NN) g_deg[i] = 0;
    if (i == 0) g_sumexp = 0.0f;
}

__global__ void k_count(const int* __restrict__ edst) {
    int e = blockIdx.x * blockDim.x + threadIdx.x;
    if (e < EE) atomicAdd(&g_deg[edst[e]], 1);
}

// ---------------- CSR build ----------------
__global__ __launch_bounds__(256) void k_scan1() {
    __shared__ int sh[256];
    int i = blockIdx.x * 256 + threadIdx.x;
    sh[threadIdx.x] = (i < NN) ? g_deg[i] : 0;
    __syncthreads();
    for (int s = 128; s > 0; s >>= 1) {
        if (threadIdx.x < s) sh[threadIdx.x] += sh[threadIdx.x + s];
        __syncthreads();
    }
    if (threadIdx.x == 0) g_part[blockIdx.x] = sh[0];
}

__global__ __launch_bounds__(512) void k_scan2() {
    __shared__ int sh[512];
    int t = threadIdx.x;
    int v = (t < SCAN_BLOCKS) ? g_part[t] : 0;
    sh[t] = v;
    __syncthreads();
    for (int s = 1; s < 512; s <<= 1) {
        int u = (t >= s) ? sh[t - s] : 0;
        __syncthreads();
        sh[t] += u;
        __syncthreads();
    }
    if (t < SCAN_BLOCKS) g_part[t] = sh[t] - v;   // exclusive
    if (t == 511) g_csr_off[NN] = sh[511];        // total == EE
}

__global__ __launch_bounds__(256) void k_scan3() {
    __shared__ int sh[256];
    int i = blockIdx.x * 256 + threadIdx.x;
    int v = (i < NN) ? g_deg[i] : 0;
    sh[threadIdx.x] = v;
    __syncthreads();
    for (int s = 1; s < 256; s <<= 1) {
        int t = (threadIdx.x >= s) ? sh[threadIdx.x - s] : 0;
        __syncthreads();
        sh[threadIdx.x] += t;
        __syncthreads();
    }
    if (i < NN) {
        int excl = sh[threadIdx.x] - v + g_part[blockIdx.x];
        g_csr_off[i] = excl;
        g_csr_pos[i] = excl;
        g_dinv[i] = rsqrtf((float)v + 1.0f);   // +1 self loop
    }
}

__global__ __launch_bounds__(256) void k_fill(const int* __restrict__ esrc,
                                              const int* __restrict__ edst) {
    int e = blockIdx.x * blockDim.x + threadIdx.x;
    if (e >= EE) return;
    int d = edst[e];
    int p = atomicAdd(&g_csr_pos[d], 1);
    g_csr_src[p] = esrc[e];
}

// ============================================================================
// GEMM via mma.sync (HMMA, bf16-split 3-term): Z = Ah*Wh + Ah*Wl + Al*Wh
// Persistent grid=148 x 256 threads, cp.async double-buffered A tiles.
// mode 0: g_zs = fp16(Z*dinv[row])   (agg init now folded into aggregate)
// mode 1: g_esc[row] = exp(tanh(Z+bias)·w2 + b2); sum -> g_sumexp
// ============================================================================
#define GEMM_GRID 148
#define BM 128
#define LDA 132              // f32 tile pitch (floats)
#define LDAH 136             // fp16 tile pitch (halfs)
#define WPITCH 68            // b32 pitch per n-row of split-W

__device__ __forceinline__ void load_tile_async(float* sA, const float* A, int row0) {
#pragma unroll
    for (int t = 0; t < 16; t++) {
        int idx = threadIdx.x + t * 256;
        int r = idx >> 5, c4 = idx & 31;
        if (row0 + r < NN)
            cp_async16(&sA[r * LDA + c4 * 4], &A[(size_t)(row0 + r) * HH + c4 * 4]);
    }
}
__device__ __forceinline__ void load_tile_async(__half* sA, const __half* A, int row0) {
#pragma unroll
    for (int t = 0; t < 8; t++) {
        int idx = threadIdx.x + t * 256;
        int r = idx >> 4, c8 = idx & 15;
        if (row0 + r < NN)
            cp_async16(&sA[r * LDAH + c8 * 8], &A[(size_t)(row0 + r) * HH + c8 * 8]);
    }
}
__device__ __forceinline__ float2 ldA(const float* sA, int r, int k) {
    return *(const float2*)&sA[r * LDA + k];
}
__device__ __forceinline__ float2 ldA(const __half* sA, int r, int k) {
    return __half22float2(*(const __half2*)&sA[r * LDAH + k]);
}

template <typename AT>
__global__ __launch_bounds__(256) void k_gemm(
    const AT* __restrict__ A, const float* __restrict__ W,
    const float* __restrict__ bias,
    const float* __restrict__ w2, const float* __restrict__ b2,
    int mode)
{
    extern __shared__ float smdyn[];
    AT* sA0 = (AT*)smdyn;
    AT* sA1 = sA0 + BM * (sizeof(AT) == 2 ? LDAH : LDA);
    uint32_t* sWh = (uint32_t*)((char*)smdyn + 2 * BM * LDA * 4);
    uint32_t* sWl = sWh + HH * WPITCH;
    __shared__ float sBias[HH];
    __shared__ float sW2[HH];
    __shared__ float sh_e;

    int tid = threadIdx.x;
    int wid = tid >> 5, lane = tid & 31;
    int g = lane >> 2, tig = lane & 3;
    int wrow = wid * 16;

    if (tid == 0) sh_e = 0.0f;
    if (tid < HH) {
        sBias[tid] = bias[tid];
        sW2[tid] = (mode == 1) ? w2[tid] : 0.0f;
    }
    float b2v = (mode == 1) ? b2[0] : 0.0f;

    load_tile_async(sA0, A, blockIdx.x * BM);
    asm volatile("cp.async.commit_group;");

    for (int idx = tid; idx < HH * 64; idx += 256) {
        int k2 = idx >> 7;
        int n  = idx & 127;
        float w0 = W[(2 * k2) * HH + n];
        float w1 = W[(2 * k2 + 1) * HH + n];
        uint32_t hi, lo;
        splitbf(w0, w1, hi, lo);
        sWh[n * WPITCH + k2] = hi;
        sWl[n * WPITCH + k2] = lo;
    }

    const int NT = (NN + BM - 1) / BM;   // 782
    float esum = 0.0f;
    int cur = 0;

    for (int tile = blockIdx.x; tile < NT; tile += GEMM_GRID) {
        AT* sA  = cur ? sA1 : sA0;
        AT* sAn = cur ? sA0 : sA1;
        int next = tile + GEMM_GRID;
        if (next < NT) {
            load_tile_async(sAn, A, next * BM);
            asm volatile("cp.async.commit_group;");
            asm volatile("cp.async.wait_group 1;");
        } else {
            asm volatile("cp.async.wait_group 0;");
        }
        __syncthreads();

        int row0 = tile * BM;
        float acc[16][4];
#pragma unroll
        for (int nt = 0; nt < 16; nt++)
#pragma unroll
            for (int j = 0; j < 4; j++) acc[nt][j] = 0.0f;

#pragma unroll 1
        for (int ks = 0; ks < 8; ks++) {
            int k0 = ks * 16;
            float2 x0 = ldA(sA, wrow + g,     k0 + tig * 2);
            float2 x1 = ldA(sA, wrow + g + 8, k0 + tig * 2);
            float2 x2 = ldA(sA, wrow + g,     k0 + 8 + tig * 2);
            float2 x3 = ldA(sA, wrow + g + 8, k0 + 8 + tig * 2);
            uint32_t ah[4], al[4];
            splitbf(x0.x, x0.y, ah[0], al[0]);
            splitbf(x1.x, x1.y, ah[1], al[1]);
            splitbf(x2.x, x2.y, ah[2], al[2]);
            splitbf(x3.x, x3.y, ah[3], al[3]);

            int kb = ks * 8 + tig;
#pragma unroll
            for (int nt = 0; nt < 16; nt++) {
                const uint32_t* rh = &sWh[(nt * 8 + g) * WPITCH];
                const uint32_t* rl = &sWl[(nt * 8 + g) * WPITCH];
                uint32_t bh0 = rh[kb], bh1 = rh[kb + 4];
                uint32_t bl0 = rl[kb], bl1 = rl[kb + 4];
                mma_bf16(acc[nt], ah, bh0, bh1);
                mma_bf16(acc[nt], ah, bl0, bl1);
                mma_bf16(acc[nt], al, bh0, bh1);
            }
        }

        // ---- epilogue ----
        int r0 = row0 + wrow + g;
        int r1 = r0 + 8;
        if (mode == 0) {
            float di0 = (r0 < NN) ? g_dinv[r0] : 0.0f;
            float di1 = (r1 < NN) ? g_dinv[r1] : 0.0f;
            size_t o0 = (size_t)r0 * HH, o1 = (size_t)r1 * HH;
#pragma unroll
            for (int nt = 0; nt < 16; nt++) {
                int c = nt * 8 + tig * 2;
                if (r0 < NN)
                    *(__half2*)&g_zs[o0 + c] =
                        __floats2half2_rn(acc[nt][0] * di0, acc[nt][1] * di0);
                if (r1 < NN)
                    *(__half2*)&g_zs[o1 + c] =
                        __floats2half2_rn(acc[nt][2] * di1, acc[nt][3] * di1);
            }
        } else {
            float p0 = 0.0f, p1 = 0.0f;
#pragma unroll
            for (int nt = 0; nt < 16; nt++) {
                int c = nt * 8 + tig * 2;
                float b0 = sBias[c], b1 = sBias[c + 1];
                float w0 = sW2[c], w1 = sW2[c + 1];
                p0 += tanhf(acc[nt][0] + b0) * w0 + tanhf(acc[nt][1] + b1) * w1;
                p1 += tanhf(acc[nt][2] + b0) * w0 + tanhf(acc[nt][3] + b1) * w1;
            }
            p0 += __shfl_xor_sync(0xffffffffu, p0, 1);
            p0 += __shfl_xor_sync(0xffffffffu, p0, 2);
            p1 += __shfl_xor_sync(0xffffffffu, p1, 1);
            p1 += __shfl_xor_sync(0xffffffffu, p1, 2);
            if (tig == 0) {
                if (r0 < NN) {
                    float e = expf(p0 + b2v);
                    g_esc[r0] = e;
                    esum += e;
                }
                if (r1 < NN) {
                    float e = expf(p1 + b2v);
                    g_esc[r1] = e;
                    esum += e;
                }
            }
        }

        __syncthreads();
        cur ^= 1;
    }

    if (mode == 1) {
        if (tig == 0) atomicAdd(&sh_e, esum);
        __syncthreads();
        if (tid == 0) atomicAdd(&g_sumexp, sh_e);
    }
}

// ---------------- aggregate (CSR gather incl. self) + bias + BN stats -----
// agg[node] = bias + dinv[node]*(zs[node] + sum_src zs[src])
#define AGG_BLOCKS 1184
__global__ __launch_bounds__(256) void k_aggregate(const float* __restrict__ bias) {
    int tid = threadIdx.x;
    int lane = tid & 31, warp = tid >> 5;
    int gw = blockIdx.x * 8 + warp;
    int nw = gridDim.x * 8;
    float4 bv = ((const float4*)bias)[lane];   // cols lane*4..lane*4+3, invariant
    float4 s4 = make_float4(0, 0, 0, 0);
    float4 q4 = make_float4(0, 0, 0, 0);

    for (int node = gw; node < NN; node += nw) {
        int beg = g_csr_off[node], end = g_csr_off[node + 1];
        // start with self row (zs[node])
        float4 acc;
        {
            uint2 raw = *(const uint2*)&g_zs[(size_t)node * HH + lane * 4];
            float2 f0 = __half22float2(*(__half2*)&raw.x);
            float2 f1 = __half22float2(*(__half2*)&raw.y);
            acc = make_float4(f0.x, f0.y, f1.x, f1.y);
        }
        for (int base = beg; base < end; base += 32) {
            int idx = base + lane;
            int s = (idx < end) ? g_csr_src[idx] : 0;
            int cnt = min(32, end - base);
            for (int j = 0; j < cnt; j++) {
                int ss = __shfl_sync(0xffffffffu, s, j);
                uint2 raw = *(const uint2*)&g_zs[(size_t)ss * HH + lane * 4];
                float2 f0 = __half22float2(*(__half2*)&raw.x);
                float2 f1 = __half22float2(*(__half2*)&raw.y);
                acc.x += f0.x; acc.y += f0.y; acc.z += f1.x; acc.w += f1.y;
            }
        }
        float di = g_dinv[node];
        float4 r = make_float4(di * acc.x + bv.x, di * acc.y + bv.y,
                               di * acc.z + bv.z, di * acc.w + bv.w);
        *(float4*)&g_agg[(size_t)node * HH + lane * 4] = r;
        s4.x += r.x; s4.y += r.y; s4.z += r.z; s4.w += r.w;
        q4.x += r.x * r.x; q4.y += r.y * r.y; q4.z += r.z * r.z; q4.w += r.w * r.w;
    }

    __shared__ float sh[8][HH];
    ((float4*)sh[warp])[lane] = s4;
    __syncthreads();
    if (tid < HH) {
        float t = 0.0f;
#pragma unroll
        for (int w = 0; w < 8; w++) t += sh[w][tid];
        atomicAdd(&g_sum[tid], t);
    }
    __syncthreads();
    ((float4*)sh[warp])[lane] = q4;
    __syncthreads();
    if (tid < HH) {
        float t = 0.0f;
#pragma unroll
        for (int w = 0; w < 8; w++) t += sh[w][tid];
        atomicAdd(&g_sumsq[tid], t);
    }
}

// ---------------- batchnorm finalize / apply ----------------
__global__ void k_bnfin(const float* __restrict__ gamma, const float* __restrict__ beta) {
    int c = threadIdx.x;
    float mean = g_sum[c] / (float)NN;
    float var = g_sumsq[c] / (float)NN - mean * mean;
    float sc = rsqrtf(var + 1e-5f) * gamma[c];
    g_scale[c] = sc;
    g_shift[c] = beta[c] - mean * sc;
    g_sum[c] = 0.0f;
    g_sumsq[c] = 0.0f;
}

__global__ __launch_bounds__(256) void k_apply(int residual) {
    int i4 = blockIdx.x * blockDim.x + threadIdx.x;
    if (i4 >= NN * 32) return;
    int c4 = i4 & 31;
    float4 v  = ((const float4*)g_agg)[i4];
    float4 sc = ((const float4*)g_scale)[c4];
    float4 sf = ((const float4*)g_shift)[c4];
    float4 r;
    r.x = fmaxf(v.x * sc.x + sf.x, 0.0f);
    r.y = fmaxf(v.y * sc.y + sf.y, 0.0f);
    r.z = fmaxf(v.z * sc.z + sf.z, 0.0f);
    r.w = fmaxf(v.w * sc.w + sf.w, 0.0f);
    if (residual) {
        uint2 raw = *(const uint2*)&g_h[(size_t)i4 * 4];
        float2 f0 = __half22float2(*(__half2*)&raw.x);
        float2 f1 = __half22float2(*(__half2*)&raw.y);
        r.x += f0.x; r.y += f0.y; r.z += f1.x; r.w += f1.y;
    }
    __half2 h0 = __floats2half2_rn(r.x, r.y);
    __half2 h1 = __floats2half2_rn(r.z, r.w);
    uint2 pack;
    pack.x = *(uint32_t*)&h0;
    pack.y = *(uint32_t*)&h1;
    *(uint2*)&g_h[(size_t)i4 * 4] = pack;
}

// ---------------- graph offsets + zero pooled ----------------
__global__ void k_gstart(const int* __restrict__ batch) {
    int g = blockIdx.x, c = threadIdx.x;
    g_pooled[g * HH + c] = 0.0f;
    if (c == 0) {
        int lo = 0, hi = NN;
        while (lo < hi) {
            int m = (lo + hi) >> 1;
            if (batch[m] < g) lo = m + 1; else hi = m;
        }
        g_gstart[g] = lo;
        if (g == 0) g_gstart[GG] = NN;
    }
}

// ---------------- pooling (weighted sums, fp16 h) ----------------
__global__ void k_pool() {
    int g = blockIdx.x >> 3;
    int part = blockIdx.x & 7;
    int s = g_gstart[g], e = g_gstart[g + 1];
    int c = threadIdx.x;
    float acc = 0.0f;
    for (int r = s + part; r < e; r += 8)
        acc += __half2float(g_h[(size_t)r * HH + c]) * g_esc[r];
    atomicAdd(&g_pooled[g * HH + c], acc);
}

// ---------------- final MLP ----------------
__global__ void k_mlp(const float* __restrict__ W1, const float* __restrict__ b1,
                      const float* __restrict__ W2, const float* __restrict__ b2,
                      float* __restrict__ out)
{
    __shared__ float p[HH];
    __shared__ float t[HH];
    int g = blockIdx.x, c = threadIdx.x;
    int cnt = g_gstart[g + 1] - g_gstart[g];
    if (cnt < 1) cnt = 1;
    float inv = 1.0f / (g_sumexp * (float)cnt);
    p[c] = g_pooled[g * HH + c] * inv;
    __syncthreads();
    float acc = b1[c];
    for (int k = 0; k < HH; k++) acc += p[k] * W1[k * HH + c];
    t[c] = fmaxf(acc, 0.0f);
    __syncthreads();
    float acc2 = b2[c];
    for (int k = 0; k < HH; k++) acc2 += t[k] * W2[k * HH + c];
    out[g * HH + c] = acc2;
}

// ---------------- host ----------------
extern "C" void kernel_launch(void* const* d_in, const int* in_sizes, int n_in,
                              void* d_out, int out_size)
{
    const float* x      = (const float*)d_in[0];
    const int*   ei     = (const int*)d_in[1];   // [2, E] int32
    const int*   batch  = (const int*)d_in[2];
    const float* conv_w = (const float*)d_in[3];
    const float* conv_b = (const float*)d_in[4];
    const float* bn_g   = (const float*)d_in[5];
    const float* bn_b   = (const float*)d_in[6];
    const float* aw1    = (const float*)d_in[7];
    const float* ab1    = (const float*)d_in[8];
    const float* aw2    = (const float*)d_in[9];
    const float* ab2    = (const float*)d_in[10];
    const float* pw1    = (const float*)d_in[11];
    const float* pb1    = (const float*)d_in[12];
    const float* pw2    = (const float*)d_in[13];
    const float* pb2    = (const float*)d_in[14];
    float* out = (float*)d_out;

    const int smem = (2 * BM * LDA + 2 * HH * WPITCH) * 4;   // 204800 B
    cudaFuncSetAttribute(k_gemm<float>,  cudaFuncAttributeMaxDynamicSharedMemorySize, smem);
    cudaFuncSetAttribute(k_gemm<__half>, cudaFuncAttributeMaxDynamicSharedMemorySize, smem);

    static __half* hptr = nullptr;
    if (hptr == nullptr) {
        void* p;
        cudaGetSymbolAddress(&p, g_h);
        hptr = (__half*)p;
    }

    // degree / norm / CSR build
    k_init <<<(NN + 255) / 256, 256>>>();
    k_count<<<(EE + 255) / 256, 256>>>(ei + EE);
    k_scan1<<<SCAN_BLOCKS, 256>>>();
    k_scan2<<<1, 512>>>();
    k_scan3<<<SCAN_BLOCKS, 256>>>();
    k_fill <<<(EE + 255) / 256, 256>>>(ei, ei + EE);

    // layer 1 (A = x, f32)
    k_gemm<float><<<GEMM_GRID, 256, smem>>>(x, conv_w, conv_b, nullptr, nullptr, 0);
    k_aggregate<<<AGG_BLOCKS, 256>>>(conv_b);
    k_bnfin<<<1, 128>>>(bn_g, bn_b);
    k_apply<<<(NN * 32 + 255) / 256, 256>>>(0);

    // layers 2,3 (A = g_h, fp16)
    for (int i = 1; i < 3; i++) {
        k_gemm<__half><<<GEMM_GRID, 256, smem>>>(hptr, conv_w + i * HH * HH,
                                                 conv_b + i * HH, nullptr, nullptr, 0);
        k_aggregate<<<AGG_BLOCKS, 256>>>(conv_b + i * HH);
        k_bnfin<<<1, 128>>>(bn_g + i * HH, bn_b + i * HH);
        k_apply<<<(NN * 32 + 255) / 256, 256>>>(1);
    }

    // attention GEMM (A = g_h fp16) with fused score epilogue
    k_gemm<__half><<<GEMM_GRID, 256, smem>>>(hptr, aw1, ab1, aw2, ab2, 1);

    // pooling
    k_gstart<<<GG, 128>>>(batch);
    k_pool<<<GG * 8, 128>>>();

    // final MLP
    k_mlp<<<GG, 128>>>(pw1, pb1, pw2, pb2, out);
}

// round 17
// speedup vs baseline: 1.9310x; 1.0680x over previous
#include <cuda_runtime.h>
#include <cuda_bf16.h>
#include <cuda_fp16.h>
#include <math.h>
#include <stdint.h>

#define NN 100000
#define EE 1600000
#define HH 128
#define GG 64
#define SCAN_BLOCKS 391            // ceil(NN/256)

// ---------------- scratch (device globals; allocation-free) ----------------
__device__ float g_dinv[NN];
__device__ int   g_deg[NN];
__device__ int   g_csr_off[NN + 1];
__device__ int   g_csr_pos[NN];
__device__ int   g_csr_src[EE];
__device__ int   g_part[SCAN_BLOCKS];
__device__ __half g_h[NN * HH];           // fp16 h
__device__ __half g_zs[NN * HH];          // fp16 zs
__device__ float g_agg[NN * HH];
__device__ float g_sum[HH];
__device__ float g_sumsq[HH];
__device__ float g_scale[HH];
__device__ float g_shift[HH];
__device__ float g_esc[NN];
__device__ float g_sumexp;
__device__ int   g_gstart[GG + 1];
__device__ float g_pooled[GG * HH];

// ---------------- helpers ----------------
__device__ __forceinline__ void cp_async16(void* smem_dst, const void* gsrc) {
    unsigned int s = (unsigned int)__cvta_generic_to_shared(smem_dst);
    asm volatile("cp.async.cg.shared.global [%0], [%1], 16;" :: "r"(s), "l"(gsrc));
}
static __device__ __forceinline__ uint32_t packbf(float e, float o) {
    uint32_t r;
    asm("cvt.rn.bf16x2.f32 %0, %1, %2;" : "=r"(r) : "f"(o), "f"(e));
    return r;
}
static __device__ __forceinline__ float2 bf2f(uint32_t p) {
    float2 r;
    r.x = __uint_as_float(p << 16);
    r.y = __uint_as_float(p & 0xffff0000u);
    return r;
}
static __device__ __forceinline__ void splitbf(float e, float o,
                                               uint32_t& hi, uint32_t& lo) {
    hi = packbf(e, o);
    float2 hf = bf2f(hi);
    lo = packbf(e - hf.x, o - hf.y);
}
static __device__ __forceinline__ void splitfp16(float e, float o,
                                                 uint32_t& hi, uint32_t& lo) {
    __half h0 = __float2half_rn(e), h1 = __float2half_rn(o);
    __half l0 = __float2half_rn(e - __half2float(h0));
    __half l1 = __float2half_rn(o - __half2float(h1));
    __half2 H = __halves2half2(h0, h1);
    __half2 L = __halves2half2(l0, l1);
    hi = *(uint32_t*)&H;
    lo = *(uint32_t*)&L;
}
static __device__ __forceinline__ void mma_bf16(float* c, const uint32_t* a,
                                                uint32_t b0, uint32_t b1) {
    asm volatile(
        "mma.sync.aligned.m16n8k16.row.col.f32.bf16.bf16.f32 "
        "{%0,%1,%2,%3}, {%4,%5,%6,%7}, {%8,%9}, {%0,%1,%2,%3};"
        : "+f"(c[0]), "+f"(c[1]), "+f"(c[2]), "+f"(c[3])
        : "r"(a[0]), "r"(a[1]), "r"(a[2]), "r"(a[3]), "r"(b0), "r"(b1));
}
static __device__ __forceinline__ void mma_f16(float* c, const uint32_t* a,
                                               uint32_t b0, uint32_t b1) {
    asm volatile(
        "mma.sync.aligned.m16n8k16.row.col.f32.f16.f16.f32 "
        "{%0,%1,%2,%3}, {%4,%5,%6,%7}, {%8,%9}, {%0,%1,%2,%3};"
        : "+f"(c[0]), "+f"(c[1]), "+f"(c[2]), "+f"(c[3])
        : "r"(a[0]), "r"(a[1]), "r"(a[2]), "r"(a[3]), "r"(b0), "r"(b1));
}

// ---------------- init / degree ----------------
__global__ void k_init() {
    int i = blockIdx.x * blockDim.x + threadIdx.x;
    if (i < NN) g_deg[i] = 0;
    if (i == 0) g_sumexp = 0.0f;
}

__global__ void k_count(const int* __restrict__ edst) {
    int e = blockIdx.x * blockDim.x + threadIdx.x;
    if (e < EE) atomicAdd(&g_deg[edst[e]], 1);
}

// ---------------- CSR build ----------------
__global__ __launch_bounds__(256) void k_scan1() {
    __shared__ int sh[256];
    int i = blockIdx.x * 256 + threadIdx.x;
    sh[threadIdx.x] = (i < NN) ? g_deg[i] : 0;
    __syncthreads();
    for (int s = 128; s > 0; s >>= 1) {
        if (threadIdx.x < s) sh[threadIdx.x] += sh[threadIdx.x + s];
        __syncthreads();
    }
    if (threadIdx.x == 0) g_part[blockIdx.x] = sh[0];
}

__global__ __launch_bounds__(512) void k_scan2() {
    __shared__ int sh[512];
    int t = threadIdx.x;
    int v = (t < SCAN_BLOCKS) ? g_part[t] : 0;
    sh[t] = v;
    __syncthreads();
    for (int s = 1; s < 512; s <<= 1) {
        int u = (t >= s) ? sh[t - s] : 0;
        __syncthreads();
        sh[t] += u;
        __syncthreads();
    }
    if (t < SCAN_BLOCKS) g_part[t] = sh[t] - v;   // exclusive
    if (t == 511) g_csr_off[NN] = sh[511];        // total == EE
}

__global__ __launch_bounds__(256) void k_scan3() {
    __shared__ int sh[256];
    int i = blockIdx.x * 256 + threadIdx.x;
    int v = (i < NN) ? g_deg[i] : 0;
    sh[threadIdx.x] = v;
    __syncthreads();
    for (int s = 1; s < 256; s <<= 1) {
        int t = (threadIdx.x >= s) ? sh[threadIdx.x - s] : 0;
        __syncthreads();
        sh[threadIdx.x] += t;
        __syncthreads();
    }
    if (i < NN) {
        int excl = sh[threadIdx.x] - v + g_part[blockIdx.x];
        g_csr_off[i] = excl;
        g_csr_pos[i] = excl;
        g_dinv[i] = rsqrtf((float)v + 1.0f);   // +1 self loop
    }
}

__global__ __launch_bounds__(256) void k_fill(const int* __restrict__ esrc,
                                              const int* __restrict__ edst) {
    int e = blockIdx.x * blockDim.x + threadIdx.x;
    if (e >= EE) return;
    int d = edst[e];
    int p = atomicAdd(&g_csr_pos[d], 1);
    g_csr_src[p] = esrc[e];
}

// ============================================================================
// GEMM via mma.sync. A=f32: 3-term bf16-split. A=fp16: 2-term f16-native
// (A fragments used raw; W split into fp16 hi/lo — exact A, 22-bit W).
// Persistent grid=148 x 256 threads, cp.async double-buffered A tiles.
// mode 0: g_zs = fp16(Z*dinv[row])
// mode 1: g_esc[row] = exp(tanh(Z+bias)·w2 + b2); sum -> g_sumexp
// ============================================================================
#define GEMM_GRID 148
#define BM 128
#define LDA 132              // f32 tile pitch (floats)
#define LDAH 136             // fp16 tile pitch (halfs)
#define WPITCH 68            // b32 pitch per n-row of split-W

__device__ __forceinline__ void load_tile_async(float* sA, const float* A, int row0) {
#pragma unroll
    for (int t = 0; t < 16; t++) {
        int idx = threadIdx.x + t * 256;
        int r = idx >> 5, c4 = idx & 31;
        if (row0 + r < NN)
            cp_async16(&sA[r * LDA + c4 * 4], &A[(size_t)(row0 + r) * HH + c4 * 4]);
    }
}
__device__ __forceinline__ void load_tile_async(__half* sA, const __half* A, int row0) {
#pragma unroll
    for (int t = 0; t < 8; t++) {
        int idx = threadIdx.x + t * 256;
        int r = idx >> 4, c8 = idx & 15;
        if (row0 + r < NN)
            cp_async16(&sA[r * LDAH + c8 * 8], &A[(size_t)(row0 + r) * HH + c8 * 8]);
    }
}

template <typename AT>
__global__ __launch_bounds__(256) void k_gemm(
    const AT* __restrict__ A, const float* __restrict__ W,
    const float* __restrict__ bias,
    const float* __restrict__ w2, const float* __restrict__ b2,
    int mode)
{
    constexpr bool HALF_A = (sizeof(AT) == 2);
    extern __shared__ float smdyn[];
    AT* sA0 = (AT*)smdyn;
    AT* sA1 = sA0 + BM * (HALF_A ? LDAH : LDA);
    uint32_t* sWh = (uint32_t*)((char*)smdyn + 2 * BM * LDA * 4);
    uint32_t* sWl = sWh + HH * WPITCH;
    __shared__ float sBias[HH];
    __shared__ float sW2[HH];
    __shared__ float sh_e;

    int tid = threadIdx.x;
    int wid = tid >> 5, lane = tid & 31;
    int g = lane >> 2, tig = lane & 3;
    int wrow = wid * 16;

    if (tid == 0) sh_e = 0.0f;
    if (tid < HH) {
        sBias[tid] = bias[tid];
        sW2[tid] = (mode == 1) ? w2[tid] : 0.0f;
    }
    float b2v = (mode == 1) ? b2[0] : 0.0f;

    load_tile_async(sA0, A, blockIdx.x * BM);
    asm volatile("cp.async.commit_group;");

    // split W once: sW*[n][k2] = {W[2k2][n], W[2k2+1][n]}
    for (int idx = tid; idx < HH * 64; idx += 256) {
        int k2 = idx >> 7;
        int n  = idx & 127;
        float w0 = W[(2 * k2) * HH + n];
        float w1 = W[(2 * k2 + 1) * HH + n];
        uint32_t hi, lo;
        if (HALF_A) splitfp16(w0, w1, hi, lo);
        else        splitbf(w0, w1, hi, lo);
        sWh[n * WPITCH + k2] = hi;
        sWl[n * WPITCH + k2] = lo;
    }

    const int NT = (NN + BM - 1) / BM;   // 782
    float esum = 0.0f;
    int cur = 0;

    for (int tile = blockIdx.x; tile < NT; tile += GEMM_GRID) {
        AT* sA  = cur ? sA1 : sA0;
        AT* sAn = cur ? sA0 : sA1;
        int next = tile + GEMM_GRID;
        if (next < NT) {
            load_tile_async(sAn, A, next * BM);
            asm volatile("cp.async.commit_group;");
            asm volatile("cp.async.wait_group 1;");
        } else {
            asm volatile("cp.async.wait_group 0;");
        }
        __syncthreads();

        int row0 = tile * BM;
        float acc[16][4];
#pragma unroll
        for (int nt = 0; nt < 16; nt++)
#pragma unroll
            for (int j = 0; j < 4; j++) acc[nt][j] = 0.0f;

#pragma unroll 1
        for (int ks = 0; ks < 8; ks++) {
            int k0 = ks * 16;
            int kb = ks * 8 + tig;
            if constexpr (HALF_A) {
                // raw fp16 fragments — no conversion
                const __half* sAh = (const __half*)sA;
                uint32_t a[4];
                a[0] = *(const uint32_t*)&sAh[(wrow + g)     * LDAH + k0 + tig * 2];
                a[1] = *(const uint32_t*)&sAh[(wrow + g + 8) * LDAH + k0 + tig * 2];
                a[2] = *(const uint32_t*)&sAh[(wrow + g)     * LDAH + k0 + 8 + tig * 2];
                a[3] = *(const uint32_t*)&sAh[(wrow + g + 8) * LDAH + k0 + 8 + tig * 2];
#pragma unroll
                for (int nt = 0; nt < 16; nt++) {
                    const uint32_t* rh = &sWh[(nt * 8 + g) * WPITCH];
                    const uint32_t* rl = &sWl[(nt * 8 + g) * WPITCH];
                    uint32_t bh0 = rh[kb], bh1 = rh[kb + 4];
                    uint32_t bl0 = rl[kb], bl1 = rl[kb + 4];
                    mma_f16(acc[nt], a, bh0, bh1);   // A*Wh
                    mma_f16(acc[nt], a, bl0, bl1);   // A*Wl
                }
            } else {
                const float* sAf = (const float*)sA;
                float2 x0 = *(const float2*)&sAf[(wrow + g)     * LDA + k0 + tig * 2];
                float2 x1 = *(const float2*)&sAf[(wrow + g + 8) * LDA + k0 + tig * 2];
                float2 x2 = *(const float2*)&sAf[(wrow + g)     * LDA + k0 + 8 + tig * 2];
                float2 x3 = *(const float2*)&sAf[(wrow + g + 8) * LDA + k0 + 8 + tig * 2];
                uint32_t ah[4], al[4];
                splitbf(x0.x, x0.y, ah[0], al[0]);
                splitbf(x1.x, x1.y, ah[1], al[1]);
                splitbf(x2.x, x2.y, ah[2], al[2]);
                splitbf(x3.x, x3.y, ah[3], al[3]);
#pragma unroll
                for (int nt = 0; nt < 16; nt++) {
                    const uint32_t* rh = &sWh[(nt * 8 + g) * WPITCH];
                    const uint32_t* rl = &sWl[(nt * 8 + g) * WPITCH];
                    uint32_t bh0 = rh[kb], bh1 = rh[kb + 4];
                    uint32_t bl0 = rl[kb], bl1 = rl[kb + 4];
                    mma_bf16(acc[nt], ah, bh0, bh1);
                    mma_bf16(acc[nt], ah, bl0, bl1);
                    mma_bf16(acc[nt], al, bh0, bh1);
                }
            }
        }

        // ---- epilogue ----
        int r0 = row0 + wrow + g;
        int r1 = r0 + 8;
        if (mode == 0) {
            float di0 = (r0 < NN) ? g_dinv[r0] : 0.0f;
            float di1 = (r1 < NN) ? g_dinv[r1] : 0.0f;
            size_t o0 = (size_t)r0 * HH, o1 = (size_t)r1 * HH;
#pragma unroll
            for (int nt = 0; nt < 16; nt++) {
                int c = nt * 8 + tig * 2;
                if (r0 < NN)
                    *(__half2*)&g_zs[o0 + c] =
                        __floats2half2_rn(acc[nt][0] * di0, acc[nt][1] * di0);
                if (r1 < NN)
                    *(__half2*)&g_zs[o1 + c] =
                        __floats2half2_rn(acc[nt][2] * di1, acc[nt][3] * di1);
            }
        } else {
            float p0 = 0.0f, p1 = 0.0f;
#pragma unroll
            for (int nt = 0; nt < 16; nt++) {
                int c = nt * 8 + tig * 2;
                float b0 = sBias[c], b1 = sBias[c + 1];
                float w0 = sW2[c], w1 = sW2[c + 1];
                p0 += tanhf(acc[nt][0] + b0) * w0 + tanhf(acc[nt][1] + b1) * w1;
                p1 += tanhf(acc[nt][2] + b0) * w0 + tanhf(acc[nt][3] + b1) * w1;
            }
            p0 += __shfl_xor_sync(0xffffffffu, p0, 1);
            p0 += __shfl_xor_sync(0xffffffffu, p0, 2);
            p1 += __shfl_xor_sync(0xffffffffu, p1, 1);
            p1 += __shfl_xor_sync(0xffffffffu, p1, 2);
            if (tig == 0) {
                if (r0 < NN) {
                    float e = expf(p0 + b2v);
                    g_esc[r0] = e;
                    esum += e;
                }
                if (r1 < NN) {
                    float e = expf(p1 + b2v);
                    g_esc[r1] = e;
                    esum += e;
                }
            }
        }

        __syncthreads();
        cur ^= 1;
    }

    if (mode == 1) {
        if (tig == 0) atomicAdd(&sh_e, esum);
        __syncthreads();
        if (tid == 0) atomicAdd(&g_sumexp, sh_e);
    }
}

// ---------------- aggregate (CSR gather incl. self) + bias + BN stats -----
#define AGG_BLOCKS 1184
__global__ __launch_bounds__(256) void k_aggregate(const float* __restrict__ bias) {
    int tid = threadIdx.x;
    int lane = tid & 31, warp = tid >> 5;
    int gw = blockIdx.x * 8 + warp;
    int nw = gridDim.x * 8;
    float4 bv = ((const float4*)bias)[lane];
    float4 s4 = make_float4(0, 0, 0, 0);
    float4 q4 = make_float4(0, 0, 0, 0);

    for (int node = gw; node < NN; node += nw) {
        int beg = g_csr_off[node], end = g_csr_off[node + 1];
        float4 acc;
        {
            uint2 raw = *(const uint2*)&g_zs[(size_t)node * HH + lane * 4];
            float2 f0 = __half22float2(*(__half2*)&raw.x);
            float2 f1 = __half22float2(*(__half2*)&raw.y);
            acc = make_float4(f0.x, f0.y, f1.x, f1.y);
        }
        for (int base = beg; base < end; base += 32) {
            int idx = base + lane;
            int s = (idx < end) ? g_csr_src[idx] : 0;
            int cnt = min(32, end - base);
            for (int j = 0; j < cnt; j++) {
                int ss = __shfl_sync(0xffffffffu, s, j);
                uint2 raw = *(const uint2*)&g_zs[(size_t)ss * HH + lane * 4];
                float2 f0 = __half22float2(*(__half2*)&raw.x);
                float2 f1 = __half22float2(*(__half2*)&raw.y);
                acc.x += f0.x; acc.y += f0.y; acc.z += f1.x; acc.w += f1.y;
            }
        }
        float di = g_dinv[node];
        float4 r = make_float4(di * acc.x + bv.x, di * acc.y + bv.y,
                               di * acc.z + bv.z, di * acc.w + bv.w);
        *(float4*)&g_agg[(size_t)node * HH + lane * 4] = r;
        s4.x += r.x; s4.y += r.y; s4.z += r.z; s4.w += r.w;
        q4.x += r.x * r.x; q4.y += r.y * r.y; q4.z += r.z * r.z; q4.w += r.w * r.w;
    }

    __shared__ float sh[8][HH];
    ((float4*)sh[warp])[lane] = s4;
    __syncthreads();
    if (tid < HH) {
        float t = 0.0f;
#pragma unroll
        for (int w = 0; w < 8; w++) t += sh[w][tid];
        atomicAdd(&g_sum[tid], t);
    }
    __syncthreads();
    ((float4*)sh[warp])[lane] = q4;
    __syncthreads();
    if (tid < HH) {
        float t = 0.0f;
#pragma unroll
        for (int w = 0; w < 8; w++) t += sh[w][tid];
        atomicAdd(&g_sumsq[tid], t);
    }
}

// ---------------- batchnorm finalize / apply ----------------
__global__ void k_bnfin(const float* __restrict__ gamma, const float* __restrict__ beta) {
    int c = threadIdx.x;
    float mean = g_sum[c] / (float)NN;
    float var = g_sumsq[c] / (float)NN - mean * mean;
    float sc = rsqrtf(var + 1e-5f) * gamma[c];
    g_scale[c] = sc;
    g_shift[c] = beta[c] - mean * sc;
    g_sum[c] = 0.0f;
    g_sumsq[c] = 0.0f;
}

__global__ __launch_bounds__(256) void k_apply(int residual) {
    int i4 = blockIdx.x * blockDim.x + threadIdx.x;
    if (i4 >= NN * 32) return;
    int c4 = i4 & 31;
    float4 v  = ((const float4*)g_agg)[i4];
    float4 sc = ((const float4*)g_scale)[c4];
    float4 sf = ((const float4*)g_shift)[c4];
    float4 r;
    r.x = fmaxf(v.x * sc.x + sf.x, 0.0f);
    r.y = fmaxf(v.y * sc.y + sf.y, 0.0f);
    r.z = fmaxf(v.z * sc.z + sf.z, 0.0f);
    r.w = fmaxf(v.w * sc.w + sf.w, 0.0f);
    if (residual) {
        uint2 raw = *(const uint2*)&g_h[(size_t)i4 * 4];
        float2 f0 = __half22float2(*(__half2*)&raw.x);
        float2 f1 = __half22float2(*(__half2*)&raw.y);
        r.x += f0.x; r.y += f0.y; r.z += f1.x; r.w += f1.y;
    }
    __half2 h0 = __floats2half2_rn(r.x, r.y);
    __half2 h1 = __floats2half2_rn(r.z, r.w);
    uint2 pack;
    pack.x = *(uint32_t*)&h0;
    pack.y = *(uint32_t*)&h1;
    *(uint2*)&g_h[(size_t)i4 * 4] = pack;
}

// ---------------- graph offsets + zero pooled ----------------
__global__ void k_gstart(const int* __restrict__ batch) {
    int g = blockIdx.x, c = threadIdx.x;
    g_pooled[g * HH + c] = 0.0f;
    if (c == 0) {
        int lo = 0, hi = NN;
        while (lo < hi) {
            int m = (lo + hi) >> 1;
            if (batch[m] < g) lo = m + 1; else hi = m;
        }
        g_gstart[g] = lo;
        if (g == 0) g_gstart[GG] = NN;
    }
}

// ---------------- pooling (weighted sums, fp16 h) ----------------
__global__ void k_pool() {
    int g = blockIdx.x >> 3;
    int part = blockIdx.x & 7;
    int s = g_gstart[g], e = g_gstart[g + 1];
    int c = threadIdx.x;
    float acc = 0.0f;
    for (int r = s + part; r < e; r += 8)
        acc += __half2float(g_h[(size_t)r * HH + c]) * g_esc[r];
    atomicAdd(&g_pooled[g * HH + c], acc);
}

// ---------------- final MLP ----------------
__global__ void k_mlp(const float* __restrict__ W1, const float* __restrict__ b1,
                      const float* __restrict__ W2, const float* __restrict__ b2,
                      float* __restrict__ out)
{
    __shared__ float p[HH];
    __shared__ float t[HH];
    int g = blockIdx.x, c = threadIdx.x;
    int cnt = g_gstart[g + 1] - g_gstart[g];
    if (cnt < 1) cnt = 1;
    float inv = 1.0f / (g_sumexp * (float)cnt);
    p[c] = g_pooled[g * HH + c] * inv;
    __syncthreads();
    float acc = b1[c];
    for (int k = 0; k < HH; k++) acc += p[k] * W1[k * HH + c];
    t[c] = fmaxf(acc, 0.0f);
    __syncthreads();
    float acc2 = b2[c];
    for (int k = 0; k < HH; k++) acc2 += t[k] * W2[k * HH + c];
    out[g * HH + c] = acc2;
}

// ---------------- host ----------------
extern "C" void kernel_launch(void* const* d_in, const int* in_sizes, int n_in,
                              void* d_out, int out_size)
{
    const float* x      = (const float*)d_in[0];
    const int*   ei     = (const int*)d_in[1];   // [2, E] int32
    const int*   batch  = (const int*)d_in[2];
    const float* conv_w = (const float*)d_in[3];
    const float* conv_b = (const float*)d_in[4];
    const float* bn_g   = (const float*)d_in[5];
    const float* bn_b   = (const float*)d_in[6];
    const float* aw1    = (const float*)d_in[7];
    const float* ab1    = (const float*)d_in[8];
    const float* aw2    = (const float*)d_in[9];
    const float* ab2    = (const float*)d_in[10];
    const float* pw1    = (const float*)d_in[11];
    const float* pb1    = (const float*)d_in[12];
    const float* pw2    = (const float*)d_in[13];
    const float* pb2    = (const float*)d_in[14];
    float* out = (float*)d_out;

    const int smem = (2 * BM * LDA + 2 * HH * WPITCH) * 4;   // 204800 B
    cudaFuncSetAttribute(k_gemm<float>,  cudaFuncAttributeMaxDynamicSharedMemorySize, smem);
    cudaFuncSetAttribute(k_gemm<__half>, cudaFuncAttributeMaxDynamicSharedMemorySize, smem);

    static __half* hptr = nullptr;
    if (hptr == nullptr) {
        void* p;
        cudaGetSymbolAddress(&p, g_h);
        hptr = (__half*)p;
    }

    // degree / norm / CSR build
    k_init <<<(NN + 255) / 256, 256>>>();
    k_count<<<(EE + 255) / 256, 256>>>(ei + EE);
    k_scan1<<<SCAN_BLOCKS, 256>>>();
    k_scan2<<<1, 512>>>();
    k_scan3<<<SCAN_BLOCKS, 256>>>();
    k_fill <<<(EE + 255) / 256, 256>>>(ei, ei + EE);

    // layer 1 (A = x, f32, 3-term bf16)
    k_gemm<float><<<GEMM_GRID, 256, smem>>>(x, conv_w, conv_b, nullptr, nullptr, 0);
    k_aggregate<<<AGG_BLOCKS, 256>>>(conv_b);
    k_bnfin<<<1, 128>>>(bn_g, bn_b);
    k_apply<<<(NN * 32 + 255) / 256, 256>>>(0);

    // layers 2,3 (A = g_h fp16, 2-term f16-native)
    for (int i = 1; i < 3; i++) {
        k_gemm<__half><<<GEMM_GRID, 256, smem>>>(hptr, conv_w + i * HH * HH,
                                                 conv_b + i * HH, nullptr, nullptr, 0);
        k_aggregate<<<AGG_BLOCKS, 256>>>(conv_b + i * HH);
        k_bnfin<<<1, 128>>>(bn_g + i * HH, bn_b + i * HH);
        k_apply<<<(NN * 32 + 255) / 256, 256>>>(1);
    }

    // attention GEMM (fp16 A, 2-term) with fused score epilogue
    k_gemm<__half><<<GEMM_GRID, 256, smem>>>(hptr, aw1, ab1, aw2, ab2, 1);

    // pooling
    k_gstart<<<GG, 128>>>(batch);
    k_pool<<<GG * 8, 128>>>();

    // final MLP
    k_mlp<<<GG, 128>>>(pw1, pb1, pw2, pb2, out);
}